// round 4
// baseline (speedup 1.0000x reference)
#include <cuda_runtime.h>
#include <cuda_bf16.h>
#include <math.h>

#define T_   4096
#define D_   1024
#define S_   32768
#define OUTW 3092
#define NCH  32     // cumsum chunks
#define CH   128    // rows per chunk

// ---------------- scratch (static device globals; no runtime allocation) ----------------
__device__ float g_q[(size_t)T_ * D_];
__device__ float g_k[(size_t)T_ * D_];
__device__ float g_v[(size_t)T_ * D_];
__device__ float g_scores[(size_t)T_ * T_];
__device__ float g_tmp[(size_t)T_ * D_];   // attn @ V
__device__ float g_ae[(size_t)T_ * D_];    // attn_embeds (after Wo)
__device__ float g_cs[(size_t)T_ * D_];    // inclusive prefix within chunk
__device__ float g_ctot[NCH * D_];         // chunk totals
__device__ float g_choff[NCH * D_];        // exclusive chunk offsets

// ---------------- packed f32x2 helpers (FFMA2 path: 128 FMA/cyc/SM) ----------------
__device__ __forceinline__ void fma2(unsigned long long& d, unsigned long long a, unsigned long long b) {
    asm("fma.rn.f32x2 %0, %1, %2, %0;" : "+l"(d) : "l"(a), "l"(b));
}
__device__ __forceinline__ unsigned long long pk(float lo, float hi) {
    unsigned long long r;
    asm("mov.b64 %0, {%1, %2};" : "=l"(r) : "f"(lo), "f"(hi));
    return r;
}
__device__ __forceinline__ void upk(float& lo, float& hi, unsigned long long v) {
    asm("mov.b64 {%0, %1}, %2;" : "=f"(lo), "=f"(hi) : "l"(v));
}

// ---------------- SGEMM tiles ----------------
#define BM 128
#define BN 128
#define BK 16

// C[M,N] = alpha * A[M,K] @ B[N,K]^T (+ bias[n])
__global__ void __launch_bounds__(256, 2)
sgemm_nt(const float* __restrict__ A, const float* __restrict__ B,
         const float* __restrict__ bias, float* __restrict__ C,
         int M, int N, int K, float alpha)
{
    __shared__ float As[BK][BM];
    __shared__ float Bs[BK][BN];
    const int tid = threadIdx.x;
    const int bm = blockIdx.y * BM;
    const int bn = blockIdx.x * BN;
    const int tx = tid & 15;       // 0..15 (n dir)
    const int ty = tid >> 4;       // 0..15 (m dir)

    unsigned long long acc[8][4];
#pragma unroll
    for (int i = 0; i < 8; i++)
#pragma unroll
        for (int j = 0; j < 4; j++) acc[i][j] = 0ULL;

    for (int k0 = 0; k0 < K; k0 += BK) {
#pragma unroll
        for (int l = 0; l < 2; l++) {
            int idx = tid + l * 256;       // 0..511
            int r = idx >> 2;              // row within tile 0..127
            int q = idx & 3;               // float4 index within BK
            float4 av = *(const float4*)&A[(size_t)(bm + r) * K + k0 + q * 4];
            As[q * 4 + 0][r] = av.x; As[q * 4 + 1][r] = av.y;
            As[q * 4 + 2][r] = av.z; As[q * 4 + 3][r] = av.w;
            float4 bv = *(const float4*)&B[(size_t)(bn + r) * K + k0 + q * 4];
            Bs[q * 4 + 0][r] = bv.x; Bs[q * 4 + 1][r] = bv.y;
            Bs[q * 4 + 2][r] = bv.z; Bs[q * 4 + 3][r] = bv.w;
        }
        __syncthreads();
#pragma unroll
        for (int kk = 0; kk < BK; kk++) {
            float4 a0 = *(const float4*)&As[kk][ty * 8];
            float4 a1 = *(const float4*)&As[kk][ty * 8 + 4];
            float4 b0 = *(const float4*)&Bs[kk][tx * 8];
            float4 b1 = *(const float4*)&Bs[kk][tx * 8 + 4];
            unsigned long long bb[4];
            bb[0] = pk(b0.x, b0.y); bb[1] = pk(b0.z, b0.w);
            bb[2] = pk(b1.x, b1.y); bb[3] = pk(b1.z, b1.w);
            float am[8] = {a0.x, a0.y, a0.z, a0.w, a1.x, a1.y, a1.z, a1.w};
#pragma unroll
            for (int i = 0; i < 8; i++) {
                unsigned long long aa = pk(am[i], am[i]);
#pragma unroll
                for (int j = 0; j < 4; j++) fma2(acc[i][j], aa, bb[j]);
            }
        }
        __syncthreads();
    }

#pragma unroll
    for (int i = 0; i < 8; i++) {
        int row = bm + ty * 8 + i;
        int col0 = bn + tx * 8;
        float o[8];
#pragma unroll
        for (int j = 0; j < 4; j++) upk(o[2 * j], o[2 * j + 1], acc[i][j]);
        if (bias) {
#pragma unroll
            for (int j = 0; j < 8; j++) o[j] = o[j] * alpha + bias[col0 + j];
        } else {
#pragma unroll
            for (int j = 0; j < 8; j++) o[j] = o[j] * alpha;
        }
        float4* cp = (float4*)&C[(size_t)row * N + col0];
        cp[0] = make_float4(o[0], o[1], o[2], o[3]);
        cp[1] = make_float4(o[4], o[5], o[6], o[7]);
    }
}

// C[M,N] = alpha * A[M,K] @ B[K,N]
__global__ void __launch_bounds__(256, 2)
sgemm_nn(const float* __restrict__ A, const float* __restrict__ B,
         float* __restrict__ C, int M, int N, int K, float alpha)
{
    __shared__ float As[BK][BM];
    __shared__ float Bs[BK][BN];
    const int tid = threadIdx.x;
    const int bm = blockIdx.y * BM;
    const int bn = blockIdx.x * BN;
    const int tx = tid & 15;
    const int ty = tid >> 4;

    unsigned long long acc[8][4];
#pragma unroll
    for (int i = 0; i < 8; i++)
#pragma unroll
        for (int j = 0; j < 4; j++) acc[i][j] = 0ULL;

    for (int k0 = 0; k0 < K; k0 += BK) {
#pragma unroll
        for (int l = 0; l < 2; l++) {
            int idx = tid + l * 256;
            {   // A tile (transpose into As)
                int r = idx >> 2;
                int q = idx & 3;
                float4 av = *(const float4*)&A[(size_t)(bm + r) * K + k0 + q * 4];
                As[q * 4 + 0][r] = av.x; As[q * 4 + 1][r] = av.y;
                As[q * 4 + 2][r] = av.z; As[q * 4 + 3][r] = av.w;
            }
            {   // B tile (natural layout)
                int r = idx >> 5;          // 0..15
                int c = (idx & 31) * 4;    // 0..124
                float4 bv = *(const float4*)&B[(size_t)(k0 + r) * N + bn + c];
                *(float4*)&Bs[r][c] = bv;
            }
        }
        __syncthreads();
#pragma unroll
        for (int kk = 0; kk < BK; kk++) {
            float4 a0 = *(const float4*)&As[kk][ty * 8];
            float4 a1 = *(const float4*)&As[kk][ty * 8 + 4];
            float4 b0 = *(const float4*)&Bs[kk][tx * 8];
            float4 b1 = *(const float4*)&Bs[kk][tx * 8 + 4];
            unsigned long long bb[4];
            bb[0] = pk(b0.x, b0.y); bb[1] = pk(b0.z, b0.w);
            bb[2] = pk(b1.x, b1.y); bb[3] = pk(b1.z, b1.w);
            float am[8] = {a0.x, a0.y, a0.z, a0.w, a1.x, a1.y, a1.z, a1.w};
#pragma unroll
            for (int i = 0; i < 8; i++) {
                unsigned long long aa = pk(am[i], am[i]);
#pragma unroll
                for (int j = 0; j < 4; j++) fma2(acc[i][j], aa, bb[j]);
            }
        }
        __syncthreads();
    }

#pragma unroll
    for (int i = 0; i < 8; i++) {
        int row = bm + ty * 8 + i;
        int col0 = bn + tx * 8;
        float o[8];
#pragma unroll
        for (int j = 0; j < 4; j++) upk(o[2 * j], o[2 * j + 1], acc[i][j]);
#pragma unroll
        for (int j = 0; j < 8; j++) o[j] *= alpha;
        float4* cp = (float4*)&C[(size_t)row * N + col0];
        cp[0] = make_float4(o[0], o[1], o[2], o[3]);
        cp[1] = make_float4(o[4], o[5], o[6], o[7]);
    }
}

// ---------------- row softmax over [T_, T_] in place ----------------
__global__ void __launch_bounds__(256)
softmax_rows(float* __restrict__ Sc)
{
    __shared__ float row[T_];
    __shared__ float red[256];
    const int tid = threadIdx.x;
    const size_t base = (size_t)blockIdx.x * T_;
    float4* r4 = (float4*)row;
    const float4* g4 = (const float4*)(Sc + base);

    float mx = -INFINITY;
    for (int i = tid; i < T_ / 4; i += 256) {
        float4 v = g4[i];
        r4[i] = v;
        mx = fmaxf(mx, fmaxf(fmaxf(v.x, v.y), fmaxf(v.z, v.w)));
    }
    red[tid] = mx; __syncthreads();
    for (int s = 128; s > 0; s >>= 1) {
        if (tid < s) red[tid] = fmaxf(red[tid], red[tid + s]);
        __syncthreads();
    }
    mx = red[0];
    __syncthreads();

    float sum = 0.f;
    for (int i = tid; i < T_; i += 256) {
        float e = expf(row[i] - mx);
        row[i] = e;
        sum += e;
    }
    red[tid] = sum; __syncthreads();
    for (int s = 128; s > 0; s >>= 1) {
        if (tid < s) red[tid] += red[tid + s];
        __syncthreads();
    }
    float inv = 1.f / red[0];
    __syncthreads();

    float4* o4 = (float4*)(Sc + base);
    for (int i = tid; i < T_ / 4; i += 256) {
        float4 v = r4[i];
        o4[i] = make_float4(v.x * inv, v.y * inv, v.z * inv, v.w * inv);
    }
}

// ---------------- chunked column-wise inclusive cumsum of g_ae ----------------
__global__ void __launch_bounds__(256)
cumsum_chunks()
{
    const int col = blockIdx.y * 256 + threadIdx.x;
    const int ch = blockIdx.x;
    const int r0 = ch * CH;
    float run = 0.f;
    for (int r = 0; r < CH; r++) {
        run += g_ae[(size_t)(r0 + r) * D_ + col];
        g_cs[(size_t)(r0 + r) * D_ + col] = run;
    }
    g_ctot[ch * D_ + col] = run;
}

__global__ void __launch_bounds__(256)
scan_totals()
{
    const int col = blockIdx.x * 256 + threadIdx.x;
    float off = 0.f;
    for (int ch = 0; ch < NCH; ch++) {
        g_choff[ch * D_ + col] = off;
        off += g_ctot[ch * D_ + col];
    }
}

// ---------------- span gather: one block per span ----------------
// Index arrays may be int32 or int64 depending on whether the reference ran
// with jax x64 enabled. Detect at runtime: if the arrays are int64 (values are
// small non-negative), every odd 32-bit word is the zero high-half. If int32,
// the odd words are actual start indices (uniform in [0, 4066)) — the chance
// that the first 32 odd words are all zero is ~(1/4066)^32 ~ 0.
__device__ __forceinline__ bool detect_i64(const int* p)
{
    int acc = 0;
#pragma unroll
    for (int j = 1; j < 64; j += 2) acc |= p[j];
    return acc == 0;
}

__global__ void __launch_bounds__(128)
gather_kernel(const float* __restrict__ states,
              const float* __restrict__ dist_embed,
              const void* __restrict__ starts_raw,
              const void* __restrict__ lens_raw,
              float* __restrict__ out)
{
    const int s = blockIdx.x;
    const int* st32 = (const int*)starts_raw;
    const bool is64 = detect_i64(st32);

    int start, len;
    if (is64) {
        start = (int)((const long long*)starts_raw)[s];
        len   = (int)((const long long*)lens_raw)[s];
    } else {
        start = st32[s];
        len   = ((const int*)lens_raw)[s];
    }
    // safety clamps (no effect for valid inputs)
    if (start < 0) start = 0;
    if (start > T_ - 1) start = T_ - 1;
    if (len < 0) len = 0;
    int end = start + len;                 // inclusive end
    if (end > T_ - 1) end = T_ - 1;

    const int L = len + 1;
    const int bin = (L > 1) + (L > 2) + (L > 3) + (L > 4) +
                    (L > 8) + (L > 16) + (L > 32) + (L > 64);

    const float4* cs4  = (const float4*)g_cs;
    const float4* off4 = (const float4*)g_choff;
    const float4* st4  = (const float4*)states;
    const float4* de4  = (const float4*)dist_embed;
    float4* o4 = (float4*)(out + (size_t)s * OUTW);

    const int te = end;
    const int ts = start - 1;

    for (int i = threadIdx.x; i < OUTW / 4; i += 128) {
        float4 v;
        if (i < 256) {
            float4 e  = cs4[(size_t)te * 256 + i];
            float4 eo = off4[(te >> 7) * 256 + i];
            v = make_float4(e.x + eo.x, e.y + eo.y, e.z + eo.z, e.w + eo.w);
            if (ts >= 0) {
                float4 b  = cs4[(size_t)ts * 256 + i];
                float4 bo = off4[(ts >> 7) * 256 + i];
                v = make_float4(v.x - b.x - bo.x, v.y - b.y - bo.y,
                                v.z - b.z - bo.z, v.w - b.w - bo.w);
            }
        } else if (i < 512) {
            v = st4[(size_t)start * 256 + (i - 256)];
        } else if (i < 768) {
            v = st4[(size_t)end * 256 + (i - 512)];
        } else {
            v = de4[bin * 5 + (i - 768)];
        }
        o4[i] = v;
    }
}

// ---------------- launch ----------------
extern "C" void kernel_launch(void* const* d_in, const int* in_sizes, int n_in,
                              void* d_out, int out_size)
{
    const float* embeds = (const float*)d_in[0];
    const float* states = (const float*)d_in[1];
    const float* Wq = (const float*)d_in[2];
    const float* bq = (const float*)d_in[3];
    const float* Wk = (const float*)d_in[4];
    const float* bk = (const float*)d_in[5];
    const float* Wv = (const float*)d_in[6];
    const float* bv = (const float*)d_in[7];
    const float* Wo = (const float*)d_in[8];
    const float* bo = (const float*)d_in[9];
    const float* dist = (const float*)d_in[10];
    const void* sp_st = d_in[11];
    const void* sp_ln = d_in[12];
    float* out = (float*)d_out;

    float *pq, *pk_, *pv, *psc, *ptmp, *pae;
    cudaGetSymbolAddress((void**)&pq,   g_q);
    cudaGetSymbolAddress((void**)&pk_,  g_k);
    cudaGetSymbolAddress((void**)&pv,   g_v);
    cudaGetSymbolAddress((void**)&psc,  g_scores);
    cudaGetSymbolAddress((void**)&ptmp, g_tmp);
    cudaGetSymbolAddress((void**)&pae,  g_ae);

    const float inv_sqrt_d = 0.03125f;  // 1/sqrt(1024)

    // QKV projections: X @ W^T + b
    sgemm_nt<<<dim3(D_ / BN, T_ / BM), 256>>>(states, Wq, bq, pq,  T_, D_, D_, 1.f);
    sgemm_nt<<<dim3(D_ / BN, T_ / BM), 256>>>(states, Wk, bk, pk_, T_, D_, D_, 1.f);
    sgemm_nt<<<dim3(D_ / BN, T_ / BM), 256>>>(embeds, Wv, bv, pv,  T_, D_, D_, 1.f);

    // scores = (Q @ K^T) / sqrt(D)
    sgemm_nt<<<dim3(T_ / BN, T_ / BM), 256>>>(pq, pk_, nullptr, psc, T_, T_, D_, inv_sqrt_d);

    // softmax over rows
    softmax_rows<<<T_, 256>>>(psc);

    // attn @ V
    sgemm_nn<<<dim3(D_ / BN, T_ / BM), 256>>>(psc, pv, ptmp, T_, D_, T_, 1.f);

    // @ Wo^T + bo
    sgemm_nt<<<dim3(D_ / BN, T_ / BM), 256>>>(ptmp, Wo, bo, pae, T_, D_, D_, 1.f);

    // column cumsum (chunked) + chunk-offset scan
    cumsum_chunks<<<dim3(NCH, D_ / 256), 256>>>();
    scan_totals<<<D_ / 256, 256>>>();

    // span features
    gather_kernel<<<S_, 128>>>(states, dist, sp_st, sp_ln, out);
}

// round 6
// speedup vs baseline: 1.8387x; 1.8387x over previous
#include <cuda_runtime.h>
#include <cuda_bf16.h>
#include <math.h>

#define T_   4096
#define D_   1024
#define S_   32768
#define OUTW 3092
#define NCH  32     // cumsum chunks
#define CH   128    // rows per chunk

// ---------------- scratch (static device globals; no runtime allocation) ----------------
__device__ float g_q[(size_t)T_ * D_];
__device__ float g_k[(size_t)T_ * D_];
__device__ float g_v[(size_t)T_ * D_];
__device__ float g_scores[(size_t)T_ * T_];
__device__ float g_tmp[(size_t)T_ * D_];   // attn @ V
__device__ float g_ae[(size_t)T_ * D_];    // attn_embeds (after Wo)
__device__ float g_cs[(size_t)T_ * D_];    // inclusive prefix within chunk
__device__ float g_ctot[NCH * D_];         // chunk totals
__device__ float g_choff[NCH * D_];        // exclusive chunk offsets

// ---------------- packed f32x2 helpers (FFMA2 path: 128 FMA/cyc/SM) ----------------
__device__ __forceinline__ void fma2(unsigned long long& d, unsigned long long a, unsigned long long b) {
    asm("fma.rn.f32x2 %0, %1, %2, %0;" : "+l"(d) : "l"(a), "l"(b));
}
__device__ __forceinline__ unsigned long long pk(float lo, float hi) {
    unsigned long long r;
    asm("mov.b64 %0, {%1, %2};" : "=l"(r) : "f"(lo), "f"(hi));
    return r;
}
__device__ __forceinline__ void upk(float& lo, float& hi, unsigned long long v) {
    asm("mov.b64 {%0, %1}, %2;" : "=f"(lo), "=f"(hi) : "l"(v));
}

// ---------------- SGEMM: 128 threads, BM=BN=128, BK=16, 8x16 thread tile ----------------
// B_KMAJOR=true : C = alpha * A[M,K] @ B[N,K]^T (+bias)   (nt)
// B_KMAJOR=false: C = alpha * A[M,K] @ B[K,N]   (+bias)   (nn)
#define BM 128
#define BN 128
#define BK 16

template<bool B_KMAJOR, bool HASBIAS>
__global__ void __launch_bounds__(128, 2)
sgemm_k(const float* __restrict__ A, const float* __restrict__ B,
        const float* __restrict__ bias, float* __restrict__ C,
        int N, int K, float alpha)
{
    __shared__ float As[2][BK][BM];
    __shared__ float Bs[2][BK][BN];
    const int tid = threadIdx.x;
    const int tx = tid & 7;        // n-group 0..7
    const int ty = tid >> 3;       // m-group 0..15
    const int bm = blockIdx.y * BM;
    const int bn = blockIdx.x * BN;

    const float* Ag = A + (size_t)(bm + tid) * K;     // one A row per thread
    const float* Bg_nt = B + (size_t)(bn + tid) * K;  // one B row per thread (nt)
    const int nn_r = tid >> 5;           // base k-row within stage (nn)
    const int nn_c = (tid & 31) * 4;     // n-column within tile (nn)
    const float* Bg_nn = B + (size_t)nn_r * N + bn + nn_c;

    float4 ra[4], rb[4];

    // ---- prologue: stage 0 ----
#pragma unroll
    for (int l = 0; l < 4; l++) {
        ra[l] = *(const float4*)(Ag + l * 4);
        if (B_KMAJOR)
            rb[l] = *(const float4*)(Bg_nt + l * 4);
        else
            rb[l] = *(const float4*)(Bg_nn + (size_t)(l * 4) * N);
    }
#pragma unroll
    for (int l = 0; l < 4; l++) {
        const float* rp = (const float*)&ra[l];
#pragma unroll
        for (int j = 0; j < 4; j++) As[0][l * 4 + j][tid] = rp[j];
        if (B_KMAJOR) {
            const float* bp = (const float*)&rb[l];
#pragma unroll
            for (int j = 0; j < 4; j++) Bs[0][l * 4 + j][tid] = bp[j];
        } else {
            *(float4*)&Bs[0][nn_r + l * 4][nn_c] = rb[l];
        }
    }
    __syncthreads();

    unsigned long long acc[8][8];
#pragma unroll
    for (int i = 0; i < 8; i++)
#pragma unroll
        for (int p = 0; p < 8; p++) acc[i][p] = 0ULL;

    const int NT = K / BK;
    for (int t = 0; t < NT; t++) {
        const int buf = t & 1;
        // issue global loads for next stage (overlap with compute)
        if (t + 1 < NT) {
            const int k0 = (t + 1) * BK;
#pragma unroll
            for (int l = 0; l < 4; l++) {
                ra[l] = *(const float4*)(Ag + k0 + l * 4);
                if (B_KMAJOR)
                    rb[l] = *(const float4*)(Bg_nt + k0 + l * 4);
                else
                    rb[l] = *(const float4*)(Bg_nn + (size_t)(k0 + l * 4) * N);
            }
        }
        // compute current stage
#pragma unroll
        for (int kk = 0; kk < BK; kk++) {
            float4 a0 = *(const float4*)&As[buf][kk][ty * 4];
            float4 a1 = *(const float4*)&As[buf][kk][64 + ty * 4];
            float4 b0 = *(const float4*)&Bs[buf][kk][tx * 4];
            float4 b1 = *(const float4*)&Bs[buf][kk][32 + tx * 4];
            float4 b2 = *(const float4*)&Bs[buf][kk][64 + tx * 4];
            float4 b3 = *(const float4*)&Bs[buf][kk][96 + tx * 4];
            unsigned long long bb[8];
            bb[0] = pk(b0.x, b0.y); bb[1] = pk(b0.z, b0.w);
            bb[2] = pk(b1.x, b1.y); bb[3] = pk(b1.z, b1.w);
            bb[4] = pk(b2.x, b2.y); bb[5] = pk(b2.z, b2.w);
            bb[6] = pk(b3.x, b3.y); bb[7] = pk(b3.z, b3.w);
            float am[8] = {a0.x, a0.y, a0.z, a0.w, a1.x, a1.y, a1.z, a1.w};
#pragma unroll
            for (int i = 0; i < 8; i++) {
                unsigned long long aa = pk(am[i], am[i]);
#pragma unroll
                for (int p = 0; p < 8; p++) fma2(acc[i][p], aa, bb[p]);
            }
        }
        // store next stage into the idle buffer
        if (t + 1 < NT) {
            const int nb = 1 - buf;
#pragma unroll
            for (int l = 0; l < 4; l++) {
                const float* rp = (const float*)&ra[l];
#pragma unroll
                for (int j = 0; j < 4; j++) As[nb][l * 4 + j][tid] = rp[j];
                if (B_KMAJOR) {
                    const float* bp = (const float*)&rb[l];
#pragma unroll
                    for (int j = 0; j < 4; j++) Bs[nb][l * 4 + j][tid] = bp[j];
                } else {
                    *(float4*)&Bs[nb][nn_r + l * 4][nn_c] = rb[l];
                }
            }
        }
        __syncthreads();
    }

    // ---- epilogue ----
#pragma unroll
    for (int i = 0; i < 8; i++) {
        const int row = bm + ((i < 4) ? (ty * 4 + i) : (64 + ty * 4 + (i - 4)));
#pragma unroll
        for (int q = 0; q < 4; q++) {
            const int col = bn + q * 32 + tx * 4;
            float o0, o1, o2, o3;
            upk(o0, o1, acc[i][q * 2]);
            upk(o2, o3, acc[i][q * 2 + 1]);
            float4 v;
            if (HASBIAS) {
                v = make_float4(o0 * alpha + bias[col],     o1 * alpha + bias[col + 1],
                                o2 * alpha + bias[col + 2], o3 * alpha + bias[col + 3]);
            } else {
                v = make_float4(o0 * alpha, o1 * alpha, o2 * alpha, o3 * alpha);
            }
            *(float4*)&C[(size_t)row * N + col] = v;
        }
    }
}

// ---------------- row softmax over [T_, T_] in place ----------------
__global__ void __launch_bounds__(256)
softmax_rows(float* __restrict__ Sc)
{
    __shared__ float row[T_];
    __shared__ float red[256];
    const int tid = threadIdx.x;
    const size_t base = (size_t)blockIdx.x * T_;
    float4* r4 = (float4*)row;
    const float4* g4 = (const float4*)(Sc + base);

    float mx = -INFINITY;
    for (int i = tid; i < T_ / 4; i += 256) {
        float4 v = g4[i];
        r4[i] = v;
        mx = fmaxf(mx, fmaxf(fmaxf(v.x, v.y), fmaxf(v.z, v.w)));
    }
    red[tid] = mx; __syncthreads();
    for (int s = 128; s > 0; s >>= 1) {
        if (tid < s) red[tid] = fmaxf(red[tid], red[tid + s]);
        __syncthreads();
    }
    mx = red[0];
    __syncthreads();

    float sum = 0.f;
    for (int i = tid; i < T_; i += 256) {
        float e = __expf(row[i] - mx);
        row[i] = e;
        sum += e;
    }
    red[tid] = sum; __syncthreads();
    for (int s = 128; s > 0; s >>= 1) {
        if (tid < s) red[tid] += red[tid + s];
        __syncthreads();
    }
    float inv = 1.f / red[0];
    __syncthreads();

    float4* o4 = (float4*)(Sc + base);
    for (int i = tid; i < T_ / 4; i += 256) {
        float4 v = r4[i];
        o4[i] = make_float4(v.x * inv, v.y * inv, v.z * inv, v.w * inv);
    }
}

// ---------------- chunked column-wise inclusive cumsum of g_ae ----------------
__global__ void __launch_bounds__(256)
cumsum_chunks()
{
    const int col = blockIdx.y * 256 + threadIdx.x;
    const int ch = blockIdx.x;
    const int r0 = ch * CH;
    float run = 0.f;
    for (int r = 0; r < CH; r++) {
        run += g_ae[(size_t)(r0 + r) * D_ + col];
        g_cs[(size_t)(r0 + r) * D_ + col] = run;
    }
    g_ctot[ch * D_ + col] = run;
}

__global__ void __launch_bounds__(256)
scan_totals()
{
    const int col = blockIdx.x * 256 + threadIdx.x;
    float off = 0.f;
    for (int ch = 0; ch < NCH; ch++) {
        g_choff[ch * D_ + col] = off;
        off += g_ctot[ch * D_ + col];
    }
}

// ---------------- span gather: one block per span ----------------
// Index arrays may be int32 or int64 depending on jax x64 mode. Detect at
// runtime: int64 small non-negative values -> all odd 32-bit words zero.
__device__ __forceinline__ bool detect_i64(const int* p)
{
    int acc = 0;
#pragma unroll
    for (int j = 1; j < 64; j += 2) acc |= p[j];
    return acc == 0;
}

__global__ void __launch_bounds__(128)
gather_kernel(const float* __restrict__ states,
              const float* __restrict__ dist_embed,
              const void* __restrict__ starts_raw,
              const void* __restrict__ lens_raw,
              float* __restrict__ out)
{
    const int s = blockIdx.x;
    const int* st32 = (const int*)starts_raw;
    const bool is64 = detect_i64(st32);

    int start, len;
    if (is64) {
        start = (int)((const long long*)starts_raw)[s];
        len   = (int)((const long long*)lens_raw)[s];
    } else {
        start = st32[s];
        len   = ((const int*)lens_raw)[s];
    }
    if (start < 0) start = 0;
    if (start > T_ - 1) start = T_ - 1;
    if (len < 0) len = 0;
    int end = start + len;
    if (end > T_ - 1) end = T_ - 1;

    const int L = len + 1;
    const int bin = (L > 1) + (L > 2) + (L > 3) + (L > 4) +
                    (L > 8) + (L > 16) + (L > 32) + (L > 64);

    const float4* cs4  = (const float4*)g_cs;
    const float4* off4 = (const float4*)g_choff;
    const float4* st4  = (const float4*)states;
    const float4* de4  = (const float4*)dist_embed;
    float4* o4 = (float4*)(out + (size_t)s * OUTW);

    const int te = end;
    const int ts = start - 1;

    for (int i = threadIdx.x; i < OUTW / 4; i += 128) {
        float4 v;
        if (i < 256) {
            float4 e  = cs4[(size_t)te * 256 + i];
            float4 eo = off4[(te >> 7) * 256 + i];
            v = make_float4(e.x + eo.x, e.y + eo.y, e.z + eo.z, e.w + eo.w);
            if (ts >= 0) {
                float4 b  = cs4[(size_t)ts * 256 + i];
                float4 bo = off4[(ts >> 7) * 256 + i];
                v = make_float4(v.x - b.x - bo.x, v.y - b.y - bo.y,
                                v.z - b.z - bo.z, v.w - b.w - bo.w);
            }
        } else if (i < 512) {
            v = st4[(size_t)start * 256 + (i - 256)];
        } else if (i < 768) {
            v = st4[(size_t)end * 256 + (i - 512)];
        } else {
            v = de4[bin * 5 + (i - 768)];
        }
        o4[i] = v;
    }
}

// ---------------- launch ----------------
extern "C" void kernel_launch(void* const* d_in, const int* in_sizes, int n_in,
                              void* d_out, int out_size)
{
    const float* embeds = (const float*)d_in[0];
    const float* states = (const float*)d_in[1];
    const float* Wq = (const float*)d_in[2];
    const float* bq = (const float*)d_in[3];
    const float* Wk = (const float*)d_in[4];
    const float* bk = (const float*)d_in[5];
    const float* Wv = (const float*)d_in[6];
    const float* bv = (const float*)d_in[7];
    const float* Wo = (const float*)d_in[8];
    const float* bo = (const float*)d_in[9];
    const float* dist = (const float*)d_in[10];
    const void* sp_st = d_in[11];
    const void* sp_ln = d_in[12];
    float* out = (float*)d_out;

    float *pq, *pk_, *pv, *psc, *ptmp, *pae;
    cudaGetSymbolAddress((void**)&pq,   g_q);
    cudaGetSymbolAddress((void**)&pk_,  g_k);
    cudaGetSymbolAddress((void**)&pv,   g_v);
    cudaGetSymbolAddress((void**)&psc,  g_scores);
    cudaGetSymbolAddress((void**)&ptmp, g_tmp);
    cudaGetSymbolAddress((void**)&pae,  g_ae);

    const float inv_sqrt_d = 0.03125f;  // 1/sqrt(1024)
    const dim3 gD(D_ / BN, T_ / BM);    // 8 x 32
    const dim3 gT(T_ / BN, T_ / BM);    // 32 x 32

    // QKV projections: X @ W^T + b
    sgemm_k<true, true><<<gD, 128>>>(states, Wq, bq, pq,  D_, D_, 1.f);
    sgemm_k<true, true><<<gD, 128>>>(states, Wk, bk, pk_, D_, D_, 1.f);
    sgemm_k<true, true><<<gD, 128>>>(embeds, Wv, bv, pv,  D_, D_, 1.f);

    // scores = (Q @ K^T) / sqrt(D)
    sgemm_k<true, false><<<gT, 128>>>(pq, pk_, nullptr, psc, T_, D_, inv_sqrt_d);

    // softmax over rows
    softmax_rows<<<T_, 256>>>(psc);

    // attn @ V   (B is [K=T, N=D] row-major)
    sgemm_k<false, false><<<gD, 128>>>(psc, pv, nullptr, ptmp, D_, T_, 1.f);

    // @ Wo^T + bo
    sgemm_k<true, true><<<gD, 128>>>(ptmp, Wo, bo, pae, D_, D_, 1.f);

    // column cumsum (chunked) + chunk-offset scan
    cumsum_chunks<<<dim3(NCH, D_ / 256), 256>>>();
    scan_totals<<<D_ / 256, 256>>>();

    // span features
    gather_kernel<<<S_, 128>>>(states, dist, sp_st, sp_ln, out);
}

// round 10
// speedup vs baseline: 3.3160x; 1.8034x over previous
#include <cuda_runtime.h>
#include <cuda_bf16.h>
#include <math.h>
#include <stdint.h>

#define T_   4096
#define D_   1024
#define S_   32768
#define OUTW 3092
#define NCH  32
#define CH   128

// ---------------- scratch (static device globals; no runtime allocation) ----------------
__device__ __nv_bfloat16 g_st_h[(size_t)T_ * D_], g_st_l[(size_t)T_ * D_];
__device__ __nv_bfloat16 g_em_h[(size_t)T_ * D_], g_em_l[(size_t)T_ * D_];
__device__ __nv_bfloat16 g_wq_h[(size_t)D_ * D_], g_wq_l[(size_t)D_ * D_];
__device__ __nv_bfloat16 g_wk_h[(size_t)D_ * D_], g_wk_l[(size_t)D_ * D_];
__device__ __nv_bfloat16 g_wv_h[(size_t)D_ * D_], g_wv_l[(size_t)D_ * D_];
__device__ __nv_bfloat16 g_wo_h[(size_t)D_ * D_], g_wo_l[(size_t)D_ * D_];
__device__ __nv_bfloat16 g_q_h[(size_t)T_ * D_],  g_q_l[(size_t)T_ * D_];
__device__ __nv_bfloat16 g_k_h[(size_t)T_ * D_],  g_k_l[(size_t)T_ * D_];
__device__ __nv_bfloat16 g_vt_h[(size_t)D_ * T_], g_vt_l[(size_t)D_ * T_];   // V^T [D,T]
__device__ __nv_bfloat16 g_tp_h[(size_t)T_ * D_], g_tp_l[(size_t)T_ * D_];   // attn@V
__device__ __nv_bfloat16 g_at_h[(size_t)T_ * T_], g_at_l[(size_t)T_ * T_];   // attn
__device__ float g_scores[(size_t)T_ * T_];
__device__ float g_ae[(size_t)T_ * D_];
__device__ float g_cs[(size_t)T_ * D_];
__device__ float g_ctot[NCH * D_];
__device__ float g_choff[NCH * D_];

// ---------------- ptx helpers (all portable sm_80-level PTX) ----------------
__device__ __forceinline__ uint32_t smem_u32(const void* p) {
    uint32_t a;
    asm("{ .reg .u64 t; cvta.to.shared.u64 t, %1; cvt.u32.u64 %0, t; }" : "=r"(a) : "l"(p));
    return a;
}
__device__ __forceinline__ void cpa16(uint32_t d, const void* g) {
    asm volatile("cp.async.cg.shared.global [%0], [%1], 16;" :: "r"(d), "l"(g) : "memory");
}
__device__ __forceinline__ void cpa_commit() {
    asm volatile("cp.async.commit_group;" ::: "memory");
}
template<int N>
__device__ __forceinline__ void cpa_wait() {
    asm volatile("cp.async.wait_group %0;" :: "n"(N) : "memory");
}
__device__ __forceinline__ void ldmx4(uint32_t& d0, uint32_t& d1, uint32_t& d2, uint32_t& d3,
                                      uint32_t a) {
    asm volatile("ldmatrix.sync.aligned.m8n8.x4.shared.b16 {%0,%1,%2,%3}, [%4];"
                 : "=r"(d0), "=r"(d1), "=r"(d2), "=r"(d3) : "r"(a));
}
__device__ __forceinline__ void mma_bf16(float* c, const uint32_t* a, uint32_t b0, uint32_t b1) {
    asm volatile(
        "mma.sync.aligned.m16n8k16.row.col.f32.bf16.bf16.f32 "
        "{%0,%1,%2,%3}, {%4,%5,%6,%7}, {%8,%9}, {%0,%1,%2,%3};"
        : "+f"(c[0]), "+f"(c[1]), "+f"(c[2]), "+f"(c[3])
        : "r"(a[0]), "r"(a[1]), "r"(a[2]), "r"(a[3]), "r"(b0), "r"(b1));
}

// ---------------- split-bf16 tensor-core GEMM (mma.sync path) ----------------
// C[M,N] = alpha * (Ah+Al)[M,K] @ (Bh+Bl)[N,K]^T (+ bias)
// OUTMODE 0: fp32 Cf ; 1: bf16 split Ch/Cl.  BIASMODE 0 none; 1 bias[n]; 2 bias[m]
#define AST 40                      // smem row stride in halves (80B; conflict-free)
#define TILE_B (128 * AST * 2)      // 10240 B per array tile
#define SOFF_AH 0
#define SOFF_AL TILE_B
#define SOFF_BH (2 * TILE_B)
#define SOFF_BL (3 * TILE_B)
#define STAGE_B (4 * TILE_B)        // 40960
#define GEMM_SMEM (2 * STAGE_B)     // 81920

template<int OUTMODE, int BIASMODE>
__global__ void __launch_bounds__(256, 1)
gemm_tc(const __nv_bfloat16* __restrict__ Ah, const __nv_bfloat16* __restrict__ Al,
        const __nv_bfloat16* __restrict__ Bh, const __nv_bfloat16* __restrict__ Bl,
        const float* __restrict__ bias,
        float* __restrict__ Cf, __nv_bfloat16* __restrict__ Ch, __nv_bfloat16* __restrict__ Cl,
        int N, int K, float alpha)
{
    extern __shared__ char smem[];
    const uint32_t sb = smem_u32(smem);
    const int tid = threadIdx.x;
    const int wid = tid >> 5, lid = tid & 31;
    const int bm = blockIdx.y * 128, bn = blockIdx.x * 128;
    const int wm = wid & 1, wn = wid >> 1;     // warp tile: 64 (m) x 32 (n)

    // global load mapping: row r = tid>>1, halves hh..hh+15 (two 16B chunks)
    const int r = tid >> 1, hh = (tid & 1) * 16;
    const __nv_bfloat16* pAh = Ah + (size_t)(bm + r) * K + hh;
    const __nv_bfloat16* pAl = Al + (size_t)(bm + r) * K + hh;
    const __nv_bfloat16* pBh = Bh + (size_t)(bn + r) * K + hh;
    const __nv_bfloat16* pBl = Bl + (size_t)(bn + r) * K + hh;
    const uint32_t sdst = sb + (uint32_t)(r * AST + hh) * 2;

    // ldmatrix lane addressing (within a tile, bytes)
    const int arow = (lid & 7) + ((lid >> 3) & 1) * 8;   // A: m8-block then k8-block
    const int acol = ((lid >> 4) & 1) * 8;
    const int brow = (lid & 7) + ((lid >> 4) & 1) * 8;   // B: k8-block then n8-block
    const int bcol = ((lid >> 3) & 1) * 8;
    const uint32_t aoff = (uint32_t)(((wm * 64 + arow) * AST + acol) * 2);
    const uint32_t boff = (uint32_t)(((wn * 32 + brow) * AST + bcol) * 2);

    float acc[4][4][4];
#pragma unroll
    for (int i = 0; i < 4; i++)
#pragma unroll
        for (int j = 0; j < 4; j++)
#pragma unroll
            for (int p = 0; p < 4; p++) acc[i][j][p] = 0.f;

    const int NT = K / 32;

    // issue stage 0
    {
        const uint32_t d = sdst;
        cpa16(d + SOFF_AH, pAh); cpa16(d + SOFF_AH + 16, pAh + 8);
        cpa16(d + SOFF_AL, pAl); cpa16(d + SOFF_AL + 16, pAl + 8);
        cpa16(d + SOFF_BH, pBh); cpa16(d + SOFF_BH + 16, pBh + 8);
        cpa16(d + SOFF_BL, pBl); cpa16(d + SOFF_BL + 16, pBl + 8);
        cpa_commit();
    }

    for (int it = 0; it < NT; it++) {
        if (it + 1 < NT) {
            const int k0 = (it + 1) * 32;
            const uint32_t d = sdst + ((it + 1) & 1) * STAGE_B;
            cpa16(d + SOFF_AH, pAh + k0); cpa16(d + SOFF_AH + 16, pAh + k0 + 8);
            cpa16(d + SOFF_AL, pAl + k0); cpa16(d + SOFF_AL + 16, pAl + k0 + 8);
            cpa16(d + SOFF_BH, pBh + k0); cpa16(d + SOFF_BH + 16, pBh + k0 + 8);
            cpa16(d + SOFF_BL, pBl + k0); cpa16(d + SOFF_BL + 16, pBl + k0 + 8);
            cpa_commit();
            cpa_wait<1>();
        } else {
            cpa_wait<0>();
        }
        __syncthreads();

        const uint32_t st = sb + (it & 1) * STAGE_B;
#pragma unroll
        for (int kk = 0; kk < 32; kk += 16) {
            uint32_t ah[16], al[16], bh[8], bl[8];
#pragma unroll
            for (int am = 0; am < 4; am++) {
                const uint32_t adr = st + aoff + (uint32_t)((am * 16 * AST + kk) * 2);
                ldmx4(ah[am * 4], ah[am * 4 + 1], ah[am * 4 + 2], ah[am * 4 + 3], adr + SOFF_AH);
                ldmx4(al[am * 4], al[am * 4 + 1], al[am * 4 + 2], al[am * 4 + 3], adr + SOFF_AL);
            }
#pragma unroll
            for (int np = 0; np < 2; np++) {
                const uint32_t bdr = st + boff + (uint32_t)((np * 16 * AST + kk) * 2);
                ldmx4(bh[np * 4], bh[np * 4 + 1], bh[np * 4 + 2], bh[np * 4 + 3], bdr + SOFF_BH);
                ldmx4(bl[np * 4], bl[np * 4 + 1], bl[np * 4 + 2], bl[np * 4 + 3], bdr + SOFF_BL);
            }
#pragma unroll
            for (int am = 0; am < 4; am++)
#pragma unroll
                for (int an = 0; an < 4; an++) {
                    mma_bf16(acc[am][an], &ah[am * 4], bh[an * 2], bh[an * 2 + 1]);
                    mma_bf16(acc[am][an], &ah[am * 4], bl[an * 2], bl[an * 2 + 1]);
                    mma_bf16(acc[am][an], &al[am * 4], bh[an * 2], bh[an * 2 + 1]);
                }
        }
        __syncthreads();
    }

    // ---- epilogue ----
#pragma unroll
    for (int am = 0; am < 4; am++) {
        const int r0 = bm + wm * 64 + am * 16 + (lid >> 2);
        const int r1 = r0 + 8;
        const float bm0 = (BIASMODE == 2) ? bias[r0] : 0.f;
        const float bm1 = (BIASMODE == 2) ? bias[r1] : 0.f;
#pragma unroll
        for (int an = 0; an < 4; an++) {
            const int col = bn + wn * 32 + an * 8 + (lid & 3) * 2;
            float v0 = acc[am][an][0] * alpha, v1 = acc[am][an][1] * alpha;
            float v2 = acc[am][an][2] * alpha, v3 = acc[am][an][3] * alpha;
            if (BIASMODE == 1) {
                const float b0 = bias[col], b1 = bias[col + 1];
                v0 += b0; v1 += b1; v2 += b0; v3 += b1;
            } else if (BIASMODE == 2) {
                v0 += bm0; v1 += bm0; v2 += bm1; v3 += bm1;
            }
            if (OUTMODE == 0) {
                *(float2*)&Cf[(size_t)r0 * N + col] = make_float2(v0, v1);
                *(float2*)&Cf[(size_t)r1 * N + col] = make_float2(v2, v3);
            } else {
                __nv_bfloat16 h0 = __float2bfloat16(v0), h1 = __float2bfloat16(v1);
                __nv_bfloat16 h2 = __float2bfloat16(v2), h3 = __float2bfloat16(v3);
                __nv_bfloat162 hp0; hp0.x = h0; hp0.y = h1;
                __nv_bfloat162 hp1; hp1.x = h2; hp1.y = h3;
                __nv_bfloat162 lp0, lp1;
                lp0.x = __float2bfloat16(v0 - __bfloat162float(h0));
                lp0.y = __float2bfloat16(v1 - __bfloat162float(h1));
                lp1.x = __float2bfloat16(v2 - __bfloat162float(h2));
                lp1.y = __float2bfloat16(v3 - __bfloat162float(h3));
                *(__nv_bfloat162*)&Ch[(size_t)r0 * N + col] = hp0;
                *(__nv_bfloat162*)&Cl[(size_t)r0 * N + col] = lp0;
                *(__nv_bfloat162*)&Ch[(size_t)r1 * N + col] = hp1;
                *(__nv_bfloat162*)&Cl[(size_t)r1 * N + col] = lp1;
            }
        }
    }
}

// ---------------- split fp32 -> (hi, lo) bf16 ----------------
__global__ void __launch_bounds__(256)
split_k(const float* __restrict__ x, __nv_bfloat16* __restrict__ h,
        __nv_bfloat16* __restrict__ l, int n4)
{
    for (int i = blockIdx.x * 256 + threadIdx.x; i < n4; i += gridDim.x * 256) {
        float4 v = ((const float4*)x)[i];
        __nv_bfloat16 h0 = __float2bfloat16(v.x), h1 = __float2bfloat16(v.y);
        __nv_bfloat16 h2 = __float2bfloat16(v.z), h3 = __float2bfloat16(v.w);
        __nv_bfloat162 hp0; hp0.x = h0; hp0.y = h1;
        __nv_bfloat162 hp1; hp1.x = h2; hp1.y = h3;
        __nv_bfloat162 lp0, lp1;
        lp0.x = __float2bfloat16(v.x - __bfloat162float(h0));
        lp0.y = __float2bfloat16(v.y - __bfloat162float(h1));
        lp1.x = __float2bfloat16(v.z - __bfloat162float(h2));
        lp1.y = __float2bfloat16(v.w - __bfloat162float(h3));
        ((__nv_bfloat162*)h)[i * 2]     = hp0;
        ((__nv_bfloat162*)h)[i * 2 + 1] = hp1;
        ((__nv_bfloat162*)l)[i * 2]     = lp0;
        ((__nv_bfloat162*)l)[i * 2 + 1] = lp1;
    }
}

// ---------------- row softmax: fp32 scores -> bf16 split attn ----------------
__global__ void __launch_bounds__(256)
softmax_rows(const float* __restrict__ Sc,
             __nv_bfloat16* __restrict__ Ah, __nv_bfloat16* __restrict__ Al)
{
    __shared__ float row[T_];
    __shared__ float red[256];
    const int tid = threadIdx.x;
    const size_t base = (size_t)blockIdx.x * T_;
    float4* r4 = (float4*)row;
    const float4* g4 = (const float4*)(Sc + base);

    float mx = -INFINITY;
    for (int i = tid; i < T_ / 4; i += 256) {
        float4 v = g4[i];
        r4[i] = v;
        mx = fmaxf(mx, fmaxf(fmaxf(v.x, v.y), fmaxf(v.z, v.w)));
    }
    red[tid] = mx; __syncthreads();
    for (int s = 128; s > 0; s >>= 1) {
        if (tid < s) red[tid] = fmaxf(red[tid], red[tid + s]);
        __syncthreads();
    }
    mx = red[0];
    __syncthreads();

    float sum = 0.f;
    for (int i = tid; i < T_; i += 256) {
        float e = __expf(row[i] - mx);
        row[i] = e;
        sum += e;
    }
    red[tid] = sum; __syncthreads();
    for (int s = 128; s > 0; s >>= 1) {
        if (tid < s) red[tid] += red[tid + s];
        __syncthreads();
    }
    const float inv = 1.f / red[0];
    __syncthreads();

    for (int i = tid * 2; i < T_; i += 512) {
        float v0 = row[i] * inv, v1 = row[i + 1] * inv;
        __nv_bfloat16 h0 = __float2bfloat16(v0), h1 = __float2bfloat16(v1);
        __nv_bfloat162 hp; hp.x = h0; hp.y = h1;
        __nv_bfloat162 lp;
        lp.x = __float2bfloat16(v0 - __bfloat162float(h0));
        lp.y = __float2bfloat16(v1 - __bfloat162float(h1));
        *(__nv_bfloat162*)(Ah + base + i) = hp;
        *(__nv_bfloat162*)(Al + base + i) = lp;
    }
}

// ---------------- chunked column-wise cumsum of g_ae ----------------
__global__ void __launch_bounds__(256)
cumsum_chunks()
{
    const int col = blockIdx.y * 256 + threadIdx.x;
    const int ch = blockIdx.x;
    const int r0 = ch * CH;
    float run = 0.f;
    for (int r = 0; r < CH; r++) {
        run += g_ae[(size_t)(r0 + r) * D_ + col];
        g_cs[(size_t)(r0 + r) * D_ + col] = run;
    }
    g_ctot[ch * D_ + col] = run;
}

__global__ void __launch_bounds__(256)
scan_totals()
{
    const int col = blockIdx.x * 256 + threadIdx.x;
    float off = 0.f;
    for (int ch = 0; ch < NCH; ch++) {
        g_choff[ch * D_ + col] = off;
        off += g_ctot[ch * D_ + col];
    }
}

// ---------------- span gather ----------------
__device__ __forceinline__ bool detect_i64(const int* p)
{
    int acc = 0;
#pragma unroll
    for (int j = 1; j < 64; j += 2) acc |= p[j];
    return acc == 0;
}

__global__ void __launch_bounds__(128)
gather_kernel(const float* __restrict__ states,
              const float* __restrict__ dist_embed,
              const void* __restrict__ starts_raw,
              const void* __restrict__ lens_raw,
              float* __restrict__ out)
{
    const int s = blockIdx.x;
    const int* st32 = (const int*)starts_raw;
    const bool is64 = detect_i64(st32);

    int start, len;
    if (is64) {
        start = (int)((const long long*)starts_raw)[s];
        len   = (int)((const long long*)lens_raw)[s];
    } else {
        start = st32[s];
        len   = ((const int*)lens_raw)[s];
    }
    if (start < 0) start = 0;
    if (start > T_ - 1) start = T_ - 1;
    if (len < 0) len = 0;
    int end = start + len;
    if (end > T_ - 1) end = T_ - 1;

    const int L = len + 1;
    const int bin = (L > 1) + (L > 2) + (L > 3) + (L > 4) +
                    (L > 8) + (L > 16) + (L > 32) + (L > 64);

    const float4* cs4  = (const float4*)g_cs;
    const float4* off4 = (const float4*)g_choff;
    const float4* st4  = (const float4*)states;
    const float4* de4  = (const float4*)dist_embed;
    float4* o4 = (float4*)(out + (size_t)s * OUTW);

    const int te = end;
    const int ts = start - 1;

    for (int i = threadIdx.x; i < OUTW / 4; i += 128) {
        float4 v;
        if (i < 256) {
            float4 e  = cs4[(size_t)te * 256 + i];
            float4 eo = off4[(te >> 7) * 256 + i];
            v = make_float4(e.x + eo.x, e.y + eo.y, e.z + eo.z, e.w + eo.w);
            if (ts >= 0) {
                float4 b  = cs4[(size_t)ts * 256 + i];
                float4 bo = off4[(ts >> 7) * 256 + i];
                v = make_float4(v.x - b.x - bo.x, v.y - b.y - bo.y,
                                v.z - b.z - bo.z, v.w - b.w - bo.w);
            }
        } else if (i < 512) {
            v = st4[(size_t)start * 256 + (i - 256)];
        } else if (i < 768) {
            v = st4[(size_t)end * 256 + (i - 512)];
        } else {
            v = de4[bin * 5 + (i - 768)];
        }
        o4[i] = v;
    }
}

// ---------------- launch ----------------
extern "C" void kernel_launch(void* const* d_in, const int* in_sizes, int n_in,
                              void* d_out, int out_size)
{
    const float* embeds = (const float*)d_in[0];
    const float* states = (const float*)d_in[1];
    const float* Wq = (const float*)d_in[2];
    const float* bq = (const float*)d_in[3];
    const float* Wk = (const float*)d_in[4];
    const float* bk = (const float*)d_in[5];
    const float* Wv = (const float*)d_in[6];
    const float* bv = (const float*)d_in[7];
    const float* Wo = (const float*)d_in[8];
    const float* bo = (const float*)d_in[9];
    const float* dist = (const float*)d_in[10];
    const void* sp_st = d_in[11];
    const void* sp_ln = d_in[12];
    float* out = (float*)d_out;

#define SYM(p, g) void* p; cudaGetSymbolAddress(&p, g)
    SYM(sth, g_st_h); SYM(stl, g_st_l); SYM(emh, g_em_h); SYM(eml, g_em_l);
    SYM(wqh, g_wq_h); SYM(wql, g_wq_l); SYM(wkh, g_wk_h); SYM(wkl, g_wk_l);
    SYM(wvh, g_wv_h); SYM(wvl, g_wv_l); SYM(woh, g_wo_h); SYM(wol, g_wo_l);
    SYM(qh, g_q_h); SYM(ql, g_q_l); SYM(kh, g_k_h); SYM(kl, g_k_l);
    SYM(vth, g_vt_h); SYM(vtl, g_vt_l); SYM(tph, g_tp_h); SYM(tpl, g_tp_l);
    SYM(ath, g_at_h); SYM(atl, g_at_l);
    SYM(psc, g_scores); SYM(pae, g_ae);
#undef SYM

    // host-side attribute sets: unconditional (no static guards per harness rules)
    cudaFuncSetAttribute(gemm_tc<1, 1>, cudaFuncAttributeMaxDynamicSharedMemorySize, GEMM_SMEM);
    cudaFuncSetAttribute(gemm_tc<1, 2>, cudaFuncAttributeMaxDynamicSharedMemorySize, GEMM_SMEM);
    cudaFuncSetAttribute(gemm_tc<0, 0>, cudaFuncAttributeMaxDynamicSharedMemorySize, GEMM_SMEM);
    cudaFuncSetAttribute(gemm_tc<1, 0>, cudaFuncAttributeMaxDynamicSharedMemorySize, GEMM_SMEM);
    cudaFuncSetAttribute(gemm_tc<0, 1>, cudaFuncAttributeMaxDynamicSharedMemorySize, GEMM_SMEM);

    typedef __nv_bfloat16 bf;
    const float inv_sqrt_d = 0.03125f;

    // split fp32 inputs into bf16 hi/lo
    split_k<<<1184, 256>>>(states, (bf*)sth, (bf*)stl, T_ * D_ / 4);
    split_k<<<1184, 256>>>(embeds, (bf*)emh, (bf*)eml, T_ * D_ / 4);
    split_k<<<592, 256>>>(Wq, (bf*)wqh, (bf*)wql, D_ * D_ / 4);
    split_k<<<592, 256>>>(Wk, (bf*)wkh, (bf*)wkl, D_ * D_ / 4);
    split_k<<<592, 256>>>(Wv, (bf*)wvh, (bf*)wvl, D_ * D_ / 4);
    split_k<<<592, 256>>>(Wo, (bf*)woh, (bf*)wol, D_ * D_ / 4);

    // q = states @ Wq^T + bq  -> split
    gemm_tc<1, 1><<<dim3(D_ / 128, T_ / 128), 256, GEMM_SMEM>>>(
        (bf*)sth, (bf*)stl, (bf*)wqh, (bf*)wql, bq, nullptr, (bf*)qh, (bf*)ql, D_, D_, 1.f);
    // k = states @ Wk^T + bk  -> split
    gemm_tc<1, 1><<<dim3(D_ / 128, T_ / 128), 256, GEMM_SMEM>>>(
        (bf*)sth, (bf*)stl, (bf*)wkh, (bf*)wkl, bk, nullptr, (bf*)kh, (bf*)kl, D_, D_, 1.f);
    // vt = Wv @ embeds^T + bv[m] -> split  (V^T, [D,T])
    gemm_tc<1, 2><<<dim3(T_ / 128, D_ / 128), 256, GEMM_SMEM>>>(
        (bf*)wvh, (bf*)wvl, (bf*)emh, (bf*)eml, bv, nullptr, (bf*)vth, (bf*)vtl, T_, D_, 1.f);
    // scores = q @ k^T / 32 -> fp32
    gemm_tc<0, 0><<<dim3(T_ / 128, T_ / 128), 256, GEMM_SMEM>>>(
        (bf*)qh, (bf*)ql, (bf*)kh, (bf*)kl, nullptr, (float*)psc, nullptr, nullptr,
        T_, D_, inv_sqrt_d);
    // softmax -> attn split
    softmax_rows<<<T_, 256>>>((const float*)psc, (bf*)ath, (bf*)atl);
    // tmp = attn @ vt^T -> split
    gemm_tc<1, 0><<<dim3(D_ / 128, T_ / 128), 256, GEMM_SMEM>>>(
        (bf*)ath, (bf*)atl, (bf*)vth, (bf*)vtl, nullptr, nullptr, (bf*)tph, (bf*)tpl,
        D_, T_, 1.f);
    // ae = tmp @ Wo^T + bo -> fp32
    gemm_tc<0, 1><<<dim3(D_ / 128, T_ / 128), 256, GEMM_SMEM>>>(
        (bf*)tph, (bf*)tpl, (bf*)woh, (bf*)wol, bo, (float*)pae, nullptr, nullptr,
        D_, D_, 1.f);

    // cumsum + span features
    cumsum_chunks<<<dim3(NCH, D_ / 256), 256>>>();
    scan_totals<<<D_ / 256, 256>>>();
    gather_kernel<<<S_, 128>>>(states, dist, sp_st, sp_ln, out);
}

// round 11
// speedup vs baseline: 3.3932x; 1.0233x over previous
#include <cuda_runtime.h>
#include <cuda_bf16.h>
#include <math.h>
#include <stdint.h>

#define T_   4096
#define D_   1024
#define S_   32768
#define OUTW 3092
#define NCH  32
#define CH   128

// ---------------- scratch (static device globals; no runtime allocation) ----------------
__device__ __nv_bfloat16 g_st_h[(size_t)T_ * D_], g_st_l[(size_t)T_ * D_];
__device__ __nv_bfloat16 g_em_h[(size_t)T_ * D_], g_em_l[(size_t)T_ * D_];
__device__ __nv_bfloat16 g_wq_h[(size_t)D_ * D_], g_wq_l[(size_t)D_ * D_];
__device__ __nv_bfloat16 g_wk_h[(size_t)D_ * D_], g_wk_l[(size_t)D_ * D_];
__device__ __nv_bfloat16 g_wv_h[(size_t)D_ * D_], g_wv_l[(size_t)D_ * D_];
__device__ __nv_bfloat16 g_wo_h[(size_t)D_ * D_], g_wo_l[(size_t)D_ * D_];
__device__ __nv_bfloat16 g_q_h[(size_t)T_ * D_],  g_q_l[(size_t)T_ * D_];
__device__ __nv_bfloat16 g_k_h[(size_t)T_ * D_],  g_k_l[(size_t)T_ * D_];
__device__ __nv_bfloat16 g_vt_h[(size_t)D_ * T_], g_vt_l[(size_t)D_ * T_];   // V^T [D,T]
__device__ __nv_bfloat16 g_tp_h[(size_t)T_ * D_], g_tp_l[(size_t)T_ * D_];   // attn@V
__device__ __nv_bfloat16 g_at_h[(size_t)T_ * T_], g_at_l[(size_t)T_ * T_];   // attn
__device__ float g_scores[(size_t)T_ * T_];
__device__ float g_ae[(size_t)T_ * D_];
__device__ float g_cs[(size_t)T_ * D_];
__device__ float g_ctot[NCH * D_];
__device__ float g_choff[NCH * D_];

// ---------------- ptx helpers (all portable sm_80-level PTX) ----------------
__device__ __forceinline__ uint32_t smem_u32(const void* p) {
    uint32_t a;
    asm("{ .reg .u64 t; cvta.to.shared.u64 t, %1; cvt.u32.u64 %0, t; }" : "=r"(a) : "l"(p));
    return a;
}
__device__ __forceinline__ void cpa16(uint32_t d, const void* g) {
    asm volatile("cp.async.cg.shared.global [%0], [%1], 16;" :: "r"(d), "l"(g) : "memory");
}
__device__ __forceinline__ void cpa_commit() {
    asm volatile("cp.async.commit_group;" ::: "memory");
}
template<int N>
__device__ __forceinline__ void cpa_wait() {
    asm volatile("cp.async.wait_group %0;" :: "n"(N) : "memory");
}
__device__ __forceinline__ void ldmx4(uint32_t& d0, uint32_t& d1, uint32_t& d2, uint32_t& d3,
                                      uint32_t a) {
    asm volatile("ldmatrix.sync.aligned.m8n8.x4.shared.b16 {%0,%1,%2,%3}, [%4];"
                 : "=r"(d0), "=r"(d1), "=r"(d2), "=r"(d3) : "r"(a));
}
__device__ __forceinline__ void mma_bf16(float* c, const uint32_t* a, uint32_t b0, uint32_t b1) {
    asm volatile(
        "mma.sync.aligned.m16n8k16.row.col.f32.bf16.bf16.f32 "
        "{%0,%1,%2,%3}, {%4,%5,%6,%7}, {%8,%9}, {%0,%1,%2,%3};"
        : "+f"(c[0]), "+f"(c[1]), "+f"(c[2]), "+f"(c[3])
        : "r"(a[0]), "r"(a[1]), "r"(a[2]), "r"(a[3]), "r"(b0), "r"(b1));
}

// ---------------- split-bf16 tensor-core GEMM (mma.sync, 3-stage cp.async) ----------------
// C[M,N] = alpha * (Ah+Al)[M,K] @ (Bh+Bl)[N,K]^T (+ bias)
// OUTMODE 0: fp32 Cf ; 1: bf16 split Ch/Cl.  BIASMODE 0 none; 1 bias[n]; 2 bias[m]
#define AST 40                      // smem row stride in halves (80B; conflict-free)
#define TILE_B (128 * AST * 2)      // 10240 B per array tile
#define SOFF_AH 0
#define SOFF_AL TILE_B
#define SOFF_BH (2 * TILE_B)
#define SOFF_BL (3 * TILE_B)
#define STAGE_B (4 * TILE_B)        // 40960
#define NSTAGE 3
#define GEMM_SMEM (NSTAGE * STAGE_B)  // 122880

template<int OUTMODE, int BIASMODE>
__global__ void __launch_bounds__(256, 1)
gemm_tc(const __nv_bfloat16* __restrict__ Ah, const __nv_bfloat16* __restrict__ Al,
        const __nv_bfloat16* __restrict__ Bh, const __nv_bfloat16* __restrict__ Bl,
        const float* __restrict__ bias,
        float* __restrict__ Cf, __nv_bfloat16* __restrict__ Ch, __nv_bfloat16* __restrict__ Cl,
        int N, int K, float alpha)
{
    extern __shared__ char smem[];
    const uint32_t sb = smem_u32(smem);
    const int tid = threadIdx.x;
    const int wid = tid >> 5, lid = tid & 31;
    const int bm = blockIdx.y * 128, bn = blockIdx.x * 128;
    const int wm = wid & 1, wn = wid >> 1;     // warp tile: 64 (m) x 32 (n)

    // global load mapping: row r = tid>>1, halves hh..hh+15 (two 16B chunks)
    const int r = tid >> 1, hh = (tid & 1) * 16;
    const __nv_bfloat16* pAh = Ah + (size_t)(bm + r) * K + hh;
    const __nv_bfloat16* pAl = Al + (size_t)(bm + r) * K + hh;
    const __nv_bfloat16* pBh = Bh + (size_t)(bn + r) * K + hh;
    const __nv_bfloat16* pBl = Bl + (size_t)(bn + r) * K + hh;
    const uint32_t sdst = sb + (uint32_t)(r * AST + hh) * 2;

    // ldmatrix lane addressing (within a tile, bytes)
    const int arow = (lid & 7) + ((lid >> 3) & 1) * 8;   // A: m8-block then k8-block
    const int acol = ((lid >> 4) & 1) * 8;
    const int brow = (lid & 7) + ((lid >> 4) & 1) * 8;   // B: k8-block then n8-block
    const int bcol = ((lid >> 3) & 1) * 8;
    const uint32_t aoff = (uint32_t)(((wm * 64 + arow) * AST + acol) * 2);
    const uint32_t boff = (uint32_t)(((wn * 32 + brow) * AST + bcol) * 2);

    float acc[4][4][4];
#pragma unroll
    for (int i = 0; i < 4; i++)
#pragma unroll
        for (int j = 0; j < 4; j++)
#pragma unroll
            for (int p = 0; p < 4; p++) acc[i][j][p] = 0.f;

    const int NT = K / 32;

    // ---- prologue: issue stages 0 and 1 ----
#pragma unroll
    for (int s = 0; s < 2; s++) {
        const int k0 = s * 32;
        const uint32_t d = sdst + s * STAGE_B;
        cpa16(d + SOFF_AH, pAh + k0); cpa16(d + SOFF_AH + 16, pAh + k0 + 8);
        cpa16(d + SOFF_AL, pAl + k0); cpa16(d + SOFF_AL + 16, pAl + k0 + 8);
        cpa16(d + SOFF_BH, pBh + k0); cpa16(d + SOFF_BH + 16, pBh + k0 + 8);
        cpa16(d + SOFF_BL, pBl + k0); cpa16(d + SOFF_BL + 16, pBl + k0 + 8);
        cpa_commit();
    }
    cpa_wait<1>();          // stage 0 ready
    __syncthreads();

    int scur = 0, snxt = 2; // compute slot, issue slot
    for (int it = 0; it < NT; it++) {
        // issue loads for stage it+2 into slot snxt (freed by iter it-1's sync)
        const bool has_next2 = (it + 2 < NT);
        if (has_next2) {
            const int k0 = (it + 2) * 32;
            const uint32_t d = sdst + snxt * STAGE_B;
            cpa16(d + SOFF_AH, pAh + k0); cpa16(d + SOFF_AH + 16, pAh + k0 + 8);
            cpa16(d + SOFF_AL, pAl + k0); cpa16(d + SOFF_AL + 16, pAl + k0 + 8);
            cpa16(d + SOFF_BH, pBh + k0); cpa16(d + SOFF_BH + 16, pBh + k0 + 8);
            cpa16(d + SOFF_BL, pBl + k0); cpa16(d + SOFF_BL + 16, pBl + k0 + 8);
            cpa_commit();
        }

        // compute current stage
        const uint32_t st = sb + scur * STAGE_B;
#pragma unroll
        for (int kk = 0; kk < 32; kk += 16) {
            uint32_t ah[16], al[16], bh[8], bl[8];
#pragma unroll
            for (int am = 0; am < 4; am++) {
                const uint32_t adr = st + aoff + (uint32_t)((am * 16 * AST + kk) * 2);
                ldmx4(ah[am * 4], ah[am * 4 + 1], ah[am * 4 + 2], ah[am * 4 + 3], adr + SOFF_AH);
                ldmx4(al[am * 4], al[am * 4 + 1], al[am * 4 + 2], al[am * 4 + 3], adr + SOFF_AL);
            }
#pragma unroll
            for (int np = 0; np < 2; np++) {
                const uint32_t bdr = st + boff + (uint32_t)((np * 16 * AST + kk) * 2);
                ldmx4(bh[np * 4], bh[np * 4 + 1], bh[np * 4 + 2], bh[np * 4 + 3], bdr + SOFF_BH);
                ldmx4(bl[np * 4], bl[np * 4 + 1], bl[np * 4 + 2], bl[np * 4 + 3], bdr + SOFF_BL);
            }
#pragma unroll
            for (int am = 0; am < 4; am++)
#pragma unroll
                for (int an = 0; an < 4; an++) {
                    mma_bf16(acc[am][an], &ah[am * 4], bh[an * 2], bh[an * 2 + 1]);
                    mma_bf16(acc[am][an], &ah[am * 4], bl[an * 2], bl[an * 2 + 1]);
                    mma_bf16(acc[am][an], &al[am * 4], bh[an * 2], bh[an * 2 + 1]);
                }
        }

        // make stage it+1 visible for next iteration; single barrier per iter
        if (has_next2) cpa_wait<1>(); else cpa_wait<0>();
        __syncthreads();

        scur = (scur == NSTAGE - 1) ? 0 : scur + 1;
        snxt = (snxt == NSTAGE - 1) ? 0 : snxt + 1;
    }

    // ---- epilogue ----
#pragma unroll
    for (int am = 0; am < 4; am++) {
        const int r0 = bm + wm * 64 + am * 16 + (lid >> 2);
        const int r1 = r0 + 8;
        const float bm0 = (BIASMODE == 2) ? bias[r0] : 0.f;
        const float bm1 = (BIASMODE == 2) ? bias[r1] : 0.f;
#pragma unroll
        for (int an = 0; an < 4; an++) {
            const int col = bn + wn * 32 + an * 8 + (lid & 3) * 2;
            float v0 = acc[am][an][0] * alpha, v1 = acc[am][an][1] * alpha;
            float v2 = acc[am][an][2] * alpha, v3 = acc[am][an][3] * alpha;
            if (BIASMODE == 1) {
                const float b0 = bias[col], b1 = bias[col + 1];
                v0 += b0; v1 += b1; v2 += b0; v3 += b1;
            } else if (BIASMODE == 2) {
                v0 += bm0; v1 += bm0; v2 += bm1; v3 += bm1;
            }
            if (OUTMODE == 0) {
                *(float2*)&Cf[(size_t)r0 * N + col] = make_float2(v0, v1);
                *(float2*)&Cf[(size_t)r1 * N + col] = make_float2(v2, v3);
            } else {
                __nv_bfloat16 h0 = __float2bfloat16(v0), h1 = __float2bfloat16(v1);
                __nv_bfloat16 h2 = __float2bfloat16(v2), h3 = __float2bfloat16(v3);
                __nv_bfloat162 hp0; hp0.x = h0; hp0.y = h1;
                __nv_bfloat162 hp1; hp1.x = h2; hp1.y = h3;
                __nv_bfloat162 lp0, lp1;
                lp0.x = __float2bfloat16(v0 - __bfloat162float(h0));
                lp0.y = __float2bfloat16(v1 - __bfloat162float(h1));
                lp1.x = __float2bfloat16(v2 - __bfloat162float(h2));
                lp1.y = __float2bfloat16(v3 - __bfloat162float(h3));
                *(__nv_bfloat162*)&Ch[(size_t)r0 * N + col] = hp0;
                *(__nv_bfloat162*)&Cl[(size_t)r0 * N + col] = lp0;
                *(__nv_bfloat162*)&Ch[(size_t)r1 * N + col] = hp1;
                *(__nv_bfloat162*)&Cl[(size_t)r1 * N + col] = lp1;
            }
        }
    }
}

// ---------------- split fp32 -> (hi, lo) bf16 ----------------
__global__ void __launch_bounds__(256)
split_k(const float* __restrict__ x, __nv_bfloat16* __restrict__ h,
        __nv_bfloat16* __restrict__ l, int n4)
{
    for (int i = blockIdx.x * 256 + threadIdx.x; i < n4; i += gridDim.x * 256) {
        float4 v = ((const float4*)x)[i];
        __nv_bfloat16 h0 = __float2bfloat16(v.x), h1 = __float2bfloat16(v.y);
        __nv_bfloat16 h2 = __float2bfloat16(v.z), h3 = __float2bfloat16(v.w);
        __nv_bfloat162 hp0; hp0.x = h0; hp0.y = h1;
        __nv_bfloat162 hp1; hp1.x = h2; hp1.y = h3;
        __nv_bfloat162 lp0, lp1;
        lp0.x = __float2bfloat16(v.x - __bfloat162float(h0));
        lp0.y = __float2bfloat16(v.y - __bfloat162float(h1));
        lp1.x = __float2bfloat16(v.z - __bfloat162float(h2));
        lp1.y = __float2bfloat16(v.w - __bfloat162float(h3));
        ((__nv_bfloat162*)h)[i * 2]     = hp0;
        ((__nv_bfloat162*)h)[i * 2 + 1] = hp1;
        ((__nv_bfloat162*)l)[i * 2]     = lp0;
        ((__nv_bfloat162*)l)[i * 2 + 1] = lp1;
    }
}

// ---------------- row softmax: fp32 scores -> bf16 split attn ----------------
__global__ void __launch_bounds__(256)
softmax_rows(const float* __restrict__ Sc,
             __nv_bfloat16* __restrict__ Ah, __nv_bfloat16* __restrict__ Al)
{
    __shared__ float row[T_];
    __shared__ float red[256];
    const int tid = threadIdx.x;
    const size_t base = (size_t)blockIdx.x * T_;
    float4* r4 = (float4*)row;
    const float4* g4 = (const float4*)(Sc + base);

    float mx = -INFINITY;
    for (int i = tid; i < T_ / 4; i += 256) {
        float4 v = g4[i];
        r4[i] = v;
        mx = fmaxf(mx, fmaxf(fmaxf(v.x, v.y), fmaxf(v.z, v.w)));
    }
    red[tid] = mx; __syncthreads();
    for (int s = 128; s > 0; s >>= 1) {
        if (tid < s) red[tid] = fmaxf(red[tid], red[tid + s]);
        __syncthreads();
    }
    mx = red[0];
    __syncthreads();

    float sum = 0.f;
    for (int i = tid; i < T_; i += 256) {
        float e = __expf(row[i] - mx);
        row[i] = e;
        sum += e;
    }
    red[tid] = sum; __syncthreads();
    for (int s = 128; s > 0; s >>= 1) {
        if (tid < s) red[tid] += red[tid + s];
        __syncthreads();
    }
    const float inv = 1.f / red[0];
    __syncthreads();

    for (int i = tid * 2; i < T_; i += 512) {
        float v0 = row[i] * inv, v1 = row[i + 1] * inv;
        __nv_bfloat16 h0 = __float2bfloat16(v0), h1 = __float2bfloat16(v1);
        __nv_bfloat162 hp; hp.x = h0; hp.y = h1;
        __nv_bfloat162 lp;
        lp.x = __float2bfloat16(v0 - __bfloat162float(h0));
        lp.y = __float2bfloat16(v1 - __bfloat162float(h1));
        *(__nv_bfloat162*)(Ah + base + i) = hp;
        *(__nv_bfloat162*)(Al + base + i) = lp;
    }
}

// ---------------- chunked column-wise cumsum of g_ae ----------------
__global__ void __launch_bounds__(256)
cumsum_chunks()
{
    const int col = blockIdx.y * 256 + threadIdx.x;
    const int ch = blockIdx.x;
    const int r0 = ch * CH;
    float run = 0.f;
    for (int r = 0; r < CH; r++) {
        run += g_ae[(size_t)(r0 + r) * D_ + col];
        g_cs[(size_t)(r0 + r) * D_ + col] = run;
    }
    g_ctot[ch * D_ + col] = run;
}

__global__ void __launch_bounds__(256)
scan_totals()
{
    const int col = blockIdx.x * 256 + threadIdx.x;
    float off = 0.f;
    for (int ch = 0; ch < NCH; ch++) {
        g_choff[ch * D_ + col] = off;
        off += g_ctot[ch * D_ + col];
    }
}

// ---------------- span gather ----------------
__device__ __forceinline__ bool detect_i64(const int* p)
{
    int acc = 0;
#pragma unroll
    for (int j = 1; j < 64; j += 2) acc |= p[j];
    return acc == 0;
}

__global__ void __launch_bounds__(128)
gather_kernel(const float* __restrict__ states,
              const float* __restrict__ dist_embed,
              const void* __restrict__ starts_raw,
              const void* __restrict__ lens_raw,
              float* __restrict__ out)
{
    const int s = blockIdx.x;
    const int* st32 = (const int*)starts_raw;
    const bool is64 = detect_i64(st32);

    int start, len;
    if (is64) {
        start = (int)((const long long*)starts_raw)[s];
        len   = (int)((const long long*)lens_raw)[s];
    } else {
        start = st32[s];
        len   = ((const int*)lens_raw)[s];
    }
    if (start < 0) start = 0;
    if (start > T_ - 1) start = T_ - 1;
    if (len < 0) len = 0;
    int end = start + len;
    if (end > T_ - 1) end = T_ - 1;

    const int L = len + 1;
    const int bin = (L > 1) + (L > 2) + (L > 3) + (L > 4) +
                    (L > 8) + (L > 16) + (L > 32) + (L > 64);

    const float4* cs4  = (const float4*)g_cs;
    const float4* off4 = (const float4*)g_choff;
    const float4* st4  = (const float4*)states;
    const float4* de4  = (const float4*)dist_embed;
    float4* o4 = (float4*)(out + (size_t)s * OUTW);

    const int te = end;
    const int ts = start - 1;

    for (int i = threadIdx.x; i < OUTW / 4; i += 128) {
        float4 v;
        if (i < 256) {
            float4 e  = cs4[(size_t)te * 256 + i];
            float4 eo = off4[(te >> 7) * 256 + i];
            v = make_float4(e.x + eo.x, e.y + eo.y, e.z + eo.z, e.w + eo.w);
            if (ts >= 0) {
                float4 b  = cs4[(size_t)ts * 256 + i];
                float4 bo = off4[(ts >> 7) * 256 + i];
                v = make_float4(v.x - b.x - bo.x, v.y - b.y - bo.y,
                                v.z - b.z - bo.z, v.w - b.w - bo.w);
            }
        } else if (i < 512) {
            v = st4[(size_t)start * 256 + (i - 256)];
        } else if (i < 768) {
            v = st4[(size_t)end * 256 + (i - 512)];
        } else {
            v = de4[bin * 5 + (i - 768)];
        }
        o4[i] = v;
    }
}

// ---------------- launch ----------------
extern "C" void kernel_launch(void* const* d_in, const int* in_sizes, int n_in,
                              void* d_out, int out_size)
{
    const float* embeds = (const float*)d_in[0];
    const float* states = (const float*)d_in[1];
    const float* Wq = (const float*)d_in[2];
    const float* bq = (const float*)d_in[3];
    const float* Wk = (const float*)d_in[4];
    const float* bk = (const float*)d_in[5];
    const float* Wv = (const float*)d_in[6];
    const float* bv = (const float*)d_in[7];
    const float* Wo = (const float*)d_in[8];
    const float* bo = (const float*)d_in[9];
    const float* dist = (const float*)d_in[10];
    const void* sp_st = d_in[11];
    const void* sp_ln = d_in[12];
    float* out = (float*)d_out;

#define SYM(p, g) void* p; cudaGetSymbolAddress(&p, g)
    SYM(sth, g_st_h); SYM(stl, g_st_l); SYM(emh, g_em_h); SYM(eml, g_em_l);
    SYM(wqh, g_wq_h); SYM(wql, g_wq_l); SYM(wkh, g_wk_h); SYM(wkl, g_wk_l);
    SYM(wvh, g_wv_h); SYM(wvl, g_wv_l); SYM(woh, g_wo_h); SYM(wol, g_wo_l);
    SYM(qh, g_q_h); SYM(ql, g_q_l); SYM(kh, g_k_h); SYM(kl, g_k_l);
    SYM(vth, g_vt_h); SYM(vtl, g_vt_l); SYM(tph, g_tp_h); SYM(tpl, g_tp_l);
    SYM(ath, g_at_h); SYM(atl, g_at_l);
    SYM(psc, g_scores); SYM(pae, g_ae);
#undef SYM

    cudaFuncSetAttribute(gemm_tc<1, 1>, cudaFuncAttributeMaxDynamicSharedMemorySize, GEMM_SMEM);
    cudaFuncSetAttribute(gemm_tc<1, 2>, cudaFuncAttributeMaxDynamicSharedMemorySize, GEMM_SMEM);
    cudaFuncSetAttribute(gemm_tc<0, 0>, cudaFuncAttributeMaxDynamicSharedMemorySize, GEMM_SMEM);
    cudaFuncSetAttribute(gemm_tc<1, 0>, cudaFuncAttributeMaxDynamicSharedMemorySize, GEMM_SMEM);
    cudaFuncSetAttribute(gemm_tc<0, 1>, cudaFuncAttributeMaxDynamicSharedMemorySize, GEMM_SMEM);

    typedef __nv_bfloat16 bf;
    const float inv_sqrt_d = 0.03125f;

    // splits first (launches 1-5), so launch 6 (ncu -s 5 -c 1 capture) is a GEMM
    split_k<<<1184, 256>>>(states, (bf*)sth, (bf*)stl, T_ * D_ / 4);
    split_k<<<1184, 256>>>(embeds, (bf*)emh, (bf*)eml, T_ * D_ / 4);
    split_k<<<592, 256>>>(Wq, (bf*)wqh, (bf*)wql, D_ * D_ / 4);
    split_k<<<592, 256>>>(Wk, (bf*)wkh, (bf*)wkl, D_ * D_ / 4);
    split_k<<<592, 256>>>(Wv, (bf*)wvh, (bf*)wvl, D_ * D_ / 4);

    // q = states @ Wq^T + bq  -> split   (launch #6: ncu capture target)
    gemm_tc<1, 1><<<dim3(D_ / 128, T_ / 128), 256, GEMM_SMEM>>>(
        (bf*)sth, (bf*)stl, (bf*)wqh, (bf*)wql, bq, nullptr, (bf*)qh, (bf*)ql, D_, D_, 1.f);
    // k = states @ Wk^T + bk  -> split
    gemm_tc<1, 1><<<dim3(D_ / 128, T_ / 128), 256, GEMM_SMEM>>>(
        (bf*)sth, (bf*)stl, (bf*)wkh, (bf*)wkl, bk, nullptr, (bf*)kh, (bf*)kl, D_, D_, 1.f);
    // vt = Wv @ embeds^T + bv[m] -> split  (V^T, [D,T])
    gemm_tc<1, 2><<<dim3(T_ / 128, D_ / 128), 256, GEMM_SMEM>>>(
        (bf*)wvh, (bf*)wvl, (bf*)emh, (bf*)eml, bv, nullptr, (bf*)vth, (bf*)vtl, T_, D_, 1.f);
    // scores = q @ k^T / 32 -> fp32
    gemm_tc<0, 0><<<dim3(T_ / 128, T_ / 128), 256, GEMM_SMEM>>>(
        (bf*)qh, (bf*)ql, (bf*)kh, (bf*)kl, nullptr, (float*)psc, nullptr, nullptr,
        T_, D_, inv_sqrt_d);
    // softmax -> attn split
    softmax_rows<<<T_, 256>>>((const float*)psc, (bf*)ath, (bf*)atl);
    // split Wo (needed only before the final GEMM)
    split_k<<<592, 256>>>(Wo, (bf*)woh, (bf*)wol, D_ * D_ / 4);
    // tmp = attn @ vt^T -> split
    gemm_tc<1, 0><<<dim3(D_ / 128, T_ / 128), 256, GEMM_SMEM>>>(
        (bf*)ath, (bf*)atl, (bf*)vth, (bf*)vtl, nullptr, nullptr, (bf*)tph, (bf*)tpl,
        D_, T_, 1.f);
    // ae = tmp @ Wo^T + bo -> fp32
    gemm_tc<0, 1><<<dim3(D_ / 128, T_ / 128), 256, GEMM_SMEM>>>(
        (bf*)tph, (bf*)tpl, (bf*)woh, (bf*)wol, bo, (float*)pae, nullptr, nullptr,
        D_, D_, 1.f);

    // cumsum + span features
    cumsum_chunks<<<dim3(NCH, D_ / 256), 256>>>();
    scan_totals<<<D_ / 256, 256>>>();
    gather_kernel<<<S_, 128>>>(states, dist, sp_st, sp_ln, out);
}

// round 16
// speedup vs baseline: 3.3937x; 1.0001x over previous
#include <cuda_runtime.h>
#include <cuda_fp16.h>
#include <math.h>
#include <stdint.h>

#define T_   4096
#define D_   1024
#define S_   32768
#define OUTW 3092
#define NCH  32
#define CH   128

// ---------------- scratch (static device globals; no runtime allocation) ----------------
__device__ __half g_st_h[(size_t)T_ * D_], g_st_l[(size_t)T_ * D_];
__device__ __half g_em_h[(size_t)T_ * D_], g_em_l[(size_t)T_ * D_];
__device__ __half g_wq_h[(size_t)D_ * D_], g_wq_l[(size_t)D_ * D_];
__device__ __half g_wk_h[(size_t)D_ * D_], g_wk_l[(size_t)D_ * D_];
__device__ __half g_wv_h[(size_t)D_ * D_], g_wv_l[(size_t)D_ * D_];
__device__ __half g_wo_h[(size_t)D_ * D_], g_wo_l[(size_t)D_ * D_];
__device__ __half g_q_h[(size_t)T_ * D_],  g_q_l[(size_t)T_ * D_];
__device__ __half g_k_h[(size_t)T_ * D_],  g_k_l[(size_t)T_ * D_];
__device__ __half g_vt_h[(size_t)D_ * T_], g_vt_l[(size_t)D_ * T_];   // V^T [D,T]
__device__ __half g_tp_h[(size_t)T_ * D_], g_tp_l[(size_t)T_ * D_];   // attn@V
__device__ __half g_at_h[(size_t)T_ * T_], g_at_l[(size_t)T_ * T_];   // attn
__device__ float g_scores[(size_t)T_ * T_];
__device__ float g_ae[(size_t)T_ * D_];
__device__ float g_cs[(size_t)T_ * D_];
__device__ float g_ctot[NCH * D_];
__device__ float g_choff[NCH * D_];

// ---------------- ptx helpers (portable sm_80-level PTX) ----------------
__device__ __forceinline__ uint32_t smem_u32(const void* p) {
    uint32_t a;
    asm("{ .reg .u64 t; cvta.to.shared.u64 t, %1; cvt.u32.u64 %0, t; }" : "=r"(a) : "l"(p));
    return a;
}
__device__ __forceinline__ void cpa16(uint32_t d, const void* g) {
    asm volatile("cp.async.cg.shared.global [%0], [%1], 16;" :: "r"(d), "l"(g) : "memory");
}
__device__ __forceinline__ void cpa_commit() {
    asm volatile("cp.async.commit_group;" ::: "memory");
}
template<int N>
__device__ __forceinline__ void cpa_wait() {
    asm volatile("cp.async.wait_group %0;" :: "n"(N) : "memory");
}
__device__ __forceinline__ void ldmx4(uint32_t& d0, uint32_t& d1, uint32_t& d2, uint32_t& d3,
                                      uint32_t a) {
    asm volatile("ldmatrix.sync.aligned.m8n8.x4.shared.b16 {%0,%1,%2,%3}, [%4];"
                 : "=r"(d0), "=r"(d1), "=r"(d2), "=r"(d3) : "r"(a));
}
// main pass: fp16 inputs, fp32 accumulate
__device__ __forceinline__ void mma_f32acc(float* c, const uint32_t* a, uint32_t b0, uint32_t b1) {
    asm volatile(
        "mma.sync.aligned.m16n8k16.row.col.f32.f16.f16.f32 "
        "{%0,%1,%2,%3}, {%4,%5,%6,%7}, {%8,%9}, {%0,%1,%2,%3};"
        : "+f"(c[0]), "+f"(c[1]), "+f"(c[2]), "+f"(c[3])
        : "r"(a[0]), "r"(a[1]), "r"(a[2]), "r"(a[3]), "r"(b0), "r"(b1));
}
// correction passes: fp16 inputs, fp16 accumulate (hypothesis: double-rate)
__device__ __forceinline__ void mma_f16acc(uint32_t* c, const uint32_t* a, uint32_t b0, uint32_t b1) {
    asm volatile(
        "mma.sync.aligned.m16n8k16.row.col.f16.f16.f16.f16 "
        "{%0,%1}, {%2,%3,%4,%5}, {%6,%7}, {%0,%1};"
        : "+r"(c[0]), "+r"(c[1])
        : "r"(a[0]), "r"(a[1]), "r"(a[2]), "r"(a[3]), "r"(b0), "r"(b1));
}

// ---------------- split-fp16 tensor-core GEMM (mma.sync, 3-stage cp.async) ----------------
// C[M,N] = alpha * (Ah+Al)[M,K] @ (Bh+Bl)[N,K]^T (+ bias)
// OUTMODE 0: fp32 Cf ; 1: fp16 split Ch/Cl.  BIASMODE 0 none; 1 bias[n]; 2 bias[m]
#define AST 40                      // smem row stride in halves (80B; conflict-free)
#define TILE_B (128 * AST * 2)      // 10240 B per array tile
#define SOFF_AH 0
#define SOFF_AL TILE_B
#define SOFF_BH (2 * TILE_B)
#define SOFF_BL (3 * TILE_B)
#define STAGE_B (4 * TILE_B)        // 40960
#define NSTAGE 3
#define GEMM_SMEM (NSTAGE * STAGE_B)  // 122880

template<int OUTMODE, int BIASMODE>
__global__ void __launch_bounds__(256, 1)
gemm_tc(const __half* __restrict__ Ah, const __half* __restrict__ Al,
        const __half* __restrict__ Bh, const __half* __restrict__ Bl,
        const float* __restrict__ bias,
        float* __restrict__ Cf, __half* __restrict__ Ch, __half* __restrict__ Cl,
        int N, int K, float alpha)
{
    extern __shared__ char smem[];
    const uint32_t sb = smem_u32(smem);
    const int tid = threadIdx.x;
    const int wid = tid >> 5, lid = tid & 31;
    const int bm = blockIdx.y * 128, bn = blockIdx.x * 128;
    const int wm = wid & 1, wn = wid >> 1;     // warp tile: 64 (m) x 32 (n)

    const int r = tid >> 1, hh = (tid & 1) * 16;
    const __half* pAh = Ah + (size_t)(bm + r) * K + hh;
    const __half* pAl = Al + (size_t)(bm + r) * K + hh;
    const __half* pBh = Bh + (size_t)(bn + r) * K + hh;
    const __half* pBl = Bl + (size_t)(bn + r) * K + hh;
    const uint32_t sdst = sb + (uint32_t)(r * AST + hh) * 2;

    const int arow = (lid & 7) + ((lid >> 3) & 1) * 8;   // A: m8-block then k8-block
    const int acol = ((lid >> 4) & 1) * 8;
    const int brow = (lid & 7) + ((lid >> 4) & 1) * 8;   // B: k8-block then n8-block
    const int bcol = ((lid >> 3) & 1) * 8;
    const uint32_t aoff = (uint32_t)(((wm * 64 + arow) * AST + acol) * 2);
    const uint32_t boff = (uint32_t)(((wn * 32 + brow) * AST + bcol) * 2);

    float acc[4][4][4];
    uint32_t acch[4][4][2];           // shared f16 accumulator for both cross terms
#pragma unroll
    for (int i = 0; i < 4; i++)
#pragma unroll
        for (int j = 0; j < 4; j++) {
#pragma unroll
            for (int p = 0; p < 4; p++) acc[i][j][p] = 0.f;
            acch[i][j][0] = 0u; acch[i][j][1] = 0u;
        }

    const int NT = K / 32;

    // prologue: issue stages 0 and 1
#pragma unroll
    for (int s = 0; s < 2; s++) {
        const int k0 = s * 32;
        const uint32_t d = sdst + s * STAGE_B;
        cpa16(d + SOFF_AH, pAh + k0); cpa16(d + SOFF_AH + 16, pAh + k0 + 8);
        cpa16(d + SOFF_AL, pAl + k0); cpa16(d + SOFF_AL + 16, pAl + k0 + 8);
        cpa16(d + SOFF_BH, pBh + k0); cpa16(d + SOFF_BH + 16, pBh + k0 + 8);
        cpa16(d + SOFF_BL, pBl + k0); cpa16(d + SOFF_BL + 16, pBl + k0 + 8);
        cpa_commit();
    }
    cpa_wait<1>();
    __syncthreads();

    int scur = 0, snxt = 2;
    for (int it = 0; it < NT; it++) {
        const bool has_next2 = (it + 2 < NT);
        if (has_next2) {
            const int k0 = (it + 2) * 32;
            const uint32_t d = sdst + snxt * STAGE_B;
            cpa16(d + SOFF_AH, pAh + k0); cpa16(d + SOFF_AH + 16, pAh + k0 + 8);
            cpa16(d + SOFF_AL, pAl + k0); cpa16(d + SOFF_AL + 16, pAl + k0 + 8);
            cpa16(d + SOFF_BH, pBh + k0); cpa16(d + SOFF_BH + 16, pBh + k0 + 8);
            cpa16(d + SOFF_BL, pBl + k0); cpa16(d + SOFF_BL + 16, pBl + k0 + 8);
            cpa_commit();
        }

        const uint32_t st = sb + scur * STAGE_B;
#pragma unroll
        for (int kk = 0; kk < 32; kk += 16) {
            uint32_t ah[16], al[16], bh[8], bl[8];
#pragma unroll
            for (int am = 0; am < 4; am++) {
                const uint32_t adr = st + aoff + (uint32_t)((am * 16 * AST + kk) * 2);
                ldmx4(ah[am * 4], ah[am * 4 + 1], ah[am * 4 + 2], ah[am * 4 + 3], adr + SOFF_AH);
                ldmx4(al[am * 4], al[am * 4 + 1], al[am * 4 + 2], al[am * 4 + 3], adr + SOFF_AL);
            }
#pragma unroll
            for (int np = 0; np < 2; np++) {
                const uint32_t bdr = st + boff + (uint32_t)((np * 16 * AST + kk) * 2);
                ldmx4(bh[np * 4], bh[np * 4 + 1], bh[np * 4 + 2], bh[np * 4 + 3], bdr + SOFF_BH);
                ldmx4(bl[np * 4], bl[np * 4 + 1], bl[np * 4 + 2], bl[np * 4 + 3], bdr + SOFF_BL);
            }
#pragma unroll
            for (int am = 0; am < 4; am++)
#pragma unroll
                for (int an = 0; an < 4; an++) {
                    mma_f32acc(acc[am][an], &ah[am * 4], bh[an * 2], bh[an * 2 + 1]);
                    mma_f16acc(acch[am][an], &ah[am * 4], bl[an * 2], bl[an * 2 + 1]);
                    mma_f16acc(acch[am][an], &al[am * 4], bh[an * 2], bh[an * 2 + 1]);
                }
        }

        if (has_next2) cpa_wait<1>(); else cpa_wait<0>();
        __syncthreads();

        scur = (scur == NSTAGE - 1) ? 0 : scur + 1;
        snxt = (snxt == NSTAGE - 1) ? 0 : snxt + 1;
    }

    // ---- epilogue ----
#pragma unroll
    for (int am = 0; am < 4; am++) {
        const int r0 = bm + wm * 64 + am * 16 + (lid >> 2);
        const int r1 = r0 + 8;
        const float bm0 = (BIASMODE == 2) ? bias[r0] : 0.f;
        const float bm1 = (BIASMODE == 2) ? bias[r1] : 0.f;
#pragma unroll
        for (int an = 0; an < 4; an++) {
            const int col = bn + wn * 32 + an * 8 + (lid & 3) * 2;
            float2 x0 = __half22float2(*(__half2*)&acch[am][an][0]);  // row r0, cols c,c+1
            float2 x1 = __half22float2(*(__half2*)&acch[am][an][1]);  // row r1
            float v0 = (acc[am][an][0] + x0.x) * alpha;
            float v1 = (acc[am][an][1] + x0.y) * alpha;
            float v2 = (acc[am][an][2] + x1.x) * alpha;
            float v3 = (acc[am][an][3] + x1.y) * alpha;
            if (BIASMODE == 1) {
                const float b0 = bias[col], b1 = bias[col + 1];
                v0 += b0; v1 += b1; v2 += b0; v3 += b1;
            } else if (BIASMODE == 2) {
                v0 += bm0; v1 += bm0; v2 += bm1; v3 += bm1;
            }
            if (OUTMODE == 0) {
                *(float2*)&Cf[(size_t)r0 * N + col] = make_float2(v0, v1);
                *(float2*)&Cf[(size_t)r1 * N + col] = make_float2(v2, v3);
            } else {
                __half h0 = __float2half_rn(v0), h1 = __float2half_rn(v1);
                __half h2 = __float2half_rn(v2), h3 = __float2half_rn(v3);
                __half2 hp0 = __halves2half2(h0, h1), hp1 = __halves2half2(h2, h3);
                __half2 lp0 = __halves2half2(__float2half_rn(v0 - __half2float(h0)),
                                             __float2half_rn(v1 - __half2float(h1)));
                __half2 lp1 = __halves2half2(__float2half_rn(v2 - __half2float(h2)),
                                             __float2half_rn(v3 - __half2float(h3)));
                *(__half2*)&Ch[(size_t)r0 * N + col] = hp0;
                *(__half2*)&Cl[(size_t)r0 * N + col] = lp0;
                *(__half2*)&Ch[(size_t)r1 * N + col] = hp1;
                *(__half2*)&Cl[(size_t)r1 * N + col] = lp1;
            }
        }
    }
}

// ---------------- fused split: all 6 fp32 inputs -> (hi, lo) fp16, one launch ----------------
struct SplitArgs {
    const float* x[6]; __half* h[6]; __half* l[6]; int n4[6];
};
__global__ void __launch_bounds__(256)
split_all(SplitArgs a, int total4)
{
    for (int i = blockIdx.x * 256 + threadIdx.x; i < total4; i += gridDim.x * 256) {
        int seg = 0, base = 0, nn = a.n4[0];
        while (i >= base + nn) { base += nn; seg++; nn = a.n4[seg]; }
        const int j = i - base;
        float4 v = ((const float4*)a.x[seg])[j];
        __half h0 = __float2half_rn(v.x), h1 = __float2half_rn(v.y);
        __half h2 = __float2half_rn(v.z), h3 = __float2half_rn(v.w);
        __half2 hp0 = __halves2half2(h0, h1), hp1 = __halves2half2(h2, h3);
        __half2 lp0 = __halves2half2(__float2half_rn(v.x - __half2float(h0)),
                                     __float2half_rn(v.y - __half2float(h1)));
        __half2 lp1 = __halves2half2(__float2half_rn(v.z - __half2float(h2)),
                                     __float2half_rn(v.w - __half2float(h3)));
        ((__half2*)a.h[seg])[j * 2]     = hp0;
        ((__half2*)a.h[seg])[j * 2 + 1] = hp1;
        ((__half2*)a.l[seg])[j * 2]     = lp0;
        ((__half2*)a.l[seg])[j * 2 + 1] = lp1;
    }
}

// ---------------- row softmax: fp32 scores -> fp16 split attn ----------------
__global__ void __launch_bounds__(256)
softmax_rows(const float* __restrict__ Sc,
             __half* __restrict__ Ah, __half* __restrict__ Al)
{
    __shared__ float row[T_];
    __shared__ float red[256];
    const int tid = threadIdx.x;
    const size_t base = (size_t)blockIdx.x * T_;
    float4* r4 = (float4*)row;
    const float4* g4 = (const float4*)(Sc + base);

    float mx = -INFINITY;
    for (int i = tid; i < T_ / 4; i += 256) {
        float4 v = g4[i];
        r4[i] = v;
        mx = fmaxf(mx, fmaxf(fmaxf(v.x, v.y), fmaxf(v.z, v.w)));
    }
    red[tid] = mx; __syncthreads();
    for (int s = 128; s > 0; s >>= 1) {
        if (tid < s) red[tid] = fmaxf(red[tid], red[tid + s]);
        __syncthreads();
    }
    mx = red[0];
    __syncthreads();

    float sum = 0.f;
    for (int i = tid; i < T_; i += 256) {
        float e = __expf(row[i] - mx);
        row[i] = e;
        sum += e;
    }
    red[tid] = sum; __syncthreads();
    for (int s = 128; s > 0; s >>= 1) {
        if (tid < s) red[tid] += red[tid + s];
        __syncthreads();
    }
    const float inv = 1.f / red[0];
    __syncthreads();

    for (int i = tid * 2; i < T_; i += 512) {
        float v0 = row[i] * inv, v1 = row[i + 1] * inv;
        __half h0 = __float2half_rn(v0), h1 = __float2half_rn(v1);
        __half2 hp = __halves2half2(h0, h1);
        __half2 lp = __halves2half2(__float2half_rn(v0 - __half2float(h0)),
                                    __float2half_rn(v1 - __half2float(h1)));
        *(__half2*)(Ah + base + i) = hp;
        *(__half2*)(Al + base + i) = lp;
    }
}

// ---------------- chunked column-wise cumsum of g_ae ----------------
__global__ void __launch_bounds__(256)
cumsum_chunks()
{
    const int col = blockIdx.y * 256 + threadIdx.x;
    const int ch = blockIdx.x;
    const int r0 = ch * CH;
    float run = 0.f;
    for (int r = 0; r < CH; r++) {
        run += g_ae[(size_t)(r0 + r) * D_ + col];
        g_cs[(size_t)(r0 + r) * D_ + col] = run;
    }
    g_ctot[ch * D_ + col] = run;
}

__global__ void __launch_bounds__(256)
scan_totals()
{
    const int col = blockIdx.x * 256 + threadIdx.x;
    float off = 0.f;
    for (int ch = 0; ch < NCH; ch++) {
        g_choff[ch * D_ + col] = off;
        off += g_ctot[ch * D_ + col];
    }
}

// ---------------- span gather ----------------
__device__ __forceinline__ bool detect_i64(const int* p)
{
    int acc = 0;
#pragma unroll
    for (int j = 1; j < 64; j += 2) acc |= p[j];
    return acc == 0;
}

__global__ void __launch_bounds__(128)
gather_kernel(const float* __restrict__ states,
              const float* __restrict__ dist_embed,
              const void* __restrict__ starts_raw,
              const void* __restrict__ lens_raw,
              float* __restrict__ out)
{
    const int s = blockIdx.x;
    const int* st32 = (const int*)starts_raw;
    const bool is64 = detect_i64(st32);

    int start, len;
    if (is64) {
        start = (int)((const long long*)starts_raw)[s];
        len   = (int)((const long long*)lens_raw)[s];
    } else {
        start = st32[s];
        len   = ((const int*)lens_raw)[s];
    }
    if (start < 0) start = 0;
    if (start > T_ - 1) start = T_ - 1;
    if (len < 0) len = 0;
    int end = start + len;
    if (end > T_ - 1) end = T_ - 1;

    const int L = len + 1;
    const int bin = (L > 1) + (L > 2) + (L > 3) + (L > 4) +
                    (L > 8) + (L > 16) + (L > 32) + (L > 64);

    const float4* cs4  = (const float4*)g_cs;
    const float4* off4 = (const float4*)g_choff;
    const float4* st4  = (const float4*)states;
    const float4* de4  = (const float4*)dist_embed;
    float4* o4 = (float4*)(out + (size_t)s * OUTW);

    const int te = end;
    const int ts = start - 1;

    for (int i = threadIdx.x; i < OUTW / 4; i += 128) {
        float4 v;
        if (i < 256) {
            float4 e  = cs4[(size_t)te * 256 + i];
            float4 eo = off4[(te >> 7) * 256 + i];
            v = make_float4(e.x + eo.x, e.y + eo.y, e.z + eo.z, e.w + eo.w);
            if (ts >= 0) {
                float4 b  = cs4[(size_t)ts * 256 + i];
                float4 bo = off4[(ts >> 7) * 256 + i];
                v = make_float4(v.x - b.x - bo.x, v.y - b.y - bo.y,
                                v.z - b.z - bo.z, v.w - b.w - bo.w);
            }
        } else if (i < 512) {
            v = st4[(size_t)start * 256 + (i - 256)];
        } else if (i < 768) {
            v = st4[(size_t)end * 256 + (i - 512)];
        } else {
            v = de4[bin * 5 + (i - 768)];
        }
        o4[i] = v;
    }
}

// ---------------- launch ----------------
extern "C" void kernel_launch(void* const* d_in, const int* in_sizes, int n_in,
                              void* d_out, int out_size)
{
    const float* embeds = (const float*)d_in[0];
    const float* states = (const float*)d_in[1];
    const float* Wq = (const float*)d_in[2];
    const float* bq = (const float*)d_in[3];
    const float* Wk = (const float*)d_in[4];
    const float* bk = (const float*)d_in[5];
    const float* Wv = (const float*)d_in[6];
    const float* bv = (const float*)d_in[7];
    const float* Wo = (const float*)d_in[8];
    const float* bo = (const float*)d_in[9];
    const float* dist = (const float*)d_in[10];
    const void* sp_st = d_in[11];
    const void* sp_ln = d_in[12];
    float* out = (float*)d_out;

#define SYM(p, g) void* p; cudaGetSymbolAddress(&p, g)
    SYM(sth, g_st_h); SYM(stl, g_st_l); SYM(emh, g_em_h); SYM(eml, g_em_l);
    SYM(wqh, g_wq_h); SYM(wql, g_wq_l); SYM(wkh, g_wk_h); SYM(wkl, g_wk_l);
    SYM(wvh, g_wv_h); SYM(wvl, g_wv_l); SYM(woh, g_wo_h); SYM(wol, g_wo_l);
    SYM(qh, g_q_h); SYM(ql, g_q_l); SYM(kh, g_k_h); SYM(kl, g_k_l);
    SYM(vth, g_vt_h); SYM(vtl, g_vt_l); SYM(tph, g_tp_h); SYM(tpl, g_tp_l);
    SYM(ath, g_at_h); SYM(atl, g_at_l);
    SYM(psc, g_scores); SYM(pae, g_ae);
#undef SYM

    cudaFuncSetAttribute(gemm_tc<1, 1>, cudaFuncAttributeMaxDynamicSharedMemorySize, GEMM_SMEM);
    cudaFuncSetAttribute(gemm_tc<1, 2>, cudaFuncAttributeMaxDynamicSharedMemorySize, GEMM_SMEM);
    cudaFuncSetAttribute(gemm_tc<0, 0>, cudaFuncAttributeMaxDynamicSharedMemorySize, GEMM_SMEM);
    cudaFuncSetAttribute(gemm_tc<1, 0>, cudaFuncAttributeMaxDynamicSharedMemorySize, GEMM_SMEM);
    cudaFuncSetAttribute(gemm_tc<0, 1>, cudaFuncAttributeMaxDynamicSharedMemorySize, GEMM_SMEM);

    typedef __half hf;
    const float inv_sqrt_d = 0.03125f;

    // one fused split launch (launch #1) so GEMMs occupy the ncu capture window
    SplitArgs sa;
    sa.x[0] = states; sa.h[0] = (hf*)sth; sa.l[0] = (hf*)stl; sa.n4[0] = T_ * D_ / 4;
    sa.x[1] = embeds; sa.h[1] = (hf*)emh; sa.l[1] = (hf*)eml; sa.n4[1] = T_ * D_ / 4;
    sa.x[2] = Wq;     sa.h[2] = (hf*)wqh; sa.l[2] = (hf*)wql; sa.n4[2] = D_ * D_ / 4;
    sa.x[3] = Wk;     sa.h[3] = (hf*)wkh; sa.l[3] = (hf*)wkl; sa.n4[3] = D_ * D_ / 4;
    sa.x[4] = Wv;     sa.h[4] = (hf*)wvh; sa.l[4] = (hf*)wvl; sa.n4[4] = D_ * D_ / 4;
    sa.x[5] = Wo;     sa.h[5] = (hf*)woh; sa.l[5] = (hf*)wol; sa.n4[5] = D_ * D_ / 4;
    const int total4 = 2 * (T_ * D_ / 4) + 4 * (D_ * D_ / 4);
    split_all<<<2048, 256>>>(sa, total4);

    // q = states @ Wq^T + bq  -> split
    gemm_tc<1, 1><<<dim3(D_ / 128, T_ / 128), 256, GEMM_SMEM>>>(
        (hf*)sth, (hf*)stl, (hf*)wqh, (hf*)wql, bq, nullptr, (hf*)qh, (hf*)ql, D_, D_, 1.f);
    // k = states @ Wk^T + bk  -> split
    gemm_tc<1, 1><<<dim3(D_ / 128, T_ / 128), 256, GEMM_SMEM>>>(
        (hf*)sth, (hf*)stl, (hf*)wkh, (hf*)wkl, bk, nullptr, (hf*)kh, (hf*)kl, D_, D_, 1.f);
    // vt = Wv @ embeds^T + bv[m] -> split  (V^T, [D,T])
    gemm_tc<1, 2><<<dim3(T_ / 128, D_ / 128), 256, GEMM_SMEM>>>(
        (hf*)wvh, (hf*)wvl, (hf*)emh, (hf*)eml, bv, nullptr, (hf*)vth, (hf*)vtl, T_, D_, 1.f);
    // scores = q @ k^T / 32 -> fp32
    gemm_tc<0, 0><<<dim3(T_ / 128, T_ / 128), 256, GEMM_SMEM>>>(
        (hf*)qh, (hf*)ql, (hf*)kh, (hf*)kl, nullptr, (float*)psc, nullptr, nullptr,
        T_, D_, inv_sqrt_d);
    // softmax -> attn split
    softmax_rows<<<T_, 256>>>((const float*)psc, (hf*)ath, (hf*)atl);
    // tmp = attn @ vt^T -> split
    gemm_tc<1, 0><<<dim3(D_ / 128, T_ / 128), 256, GEMM_SMEM>>>(
        (hf*)ath, (hf*)atl, (hf*)vth, (hf*)vtl, nullptr, nullptr, (hf*)tph, (hf*)tpl,
        D_, T_, 1.f);
    // ae = tmp @ Wo^T + bo -> fp32
    gemm_tc<0, 1><<<dim3(D_ / 128, T_ / 128), 256, GEMM_SMEM>>>(
        (hf*)tph, (hf*)tpl, (hf*)woh, (hf*)wol, bo, (float*)pae, nullptr, nullptr,
        D_, D_, 1.f);

    // cumsum + span features
    cumsum_chunks<<<dim3(NCH, D_ / 256), 256>>>();
    scan_totals<<<D_ / 256, 256>>>();
    gather_kernel<<<S_, 128>>>(states, dist, sp_st, sp_ln, out);
}